// round 12
// baseline (speedup 1.0000x reference)
#include <cuda_runtime.h>
#include <cuda_fp16.h>
#include <cuda_bf16.h>
#include <mma.h>
#include <cstdint>

using namespace nvcuda;

#define NA 50000
#define NP 100000
#define DA 512
#define DP 256
#define HH 64
#define NOUT 16
#define NHOP 3
#define EMAX 2000000

// ------------------------- device scratch (static; no allocs) ----------------
__device__ float g_xa[NA * HH];
__device__ float g_xp[NP * HH];
__device__ __half g_ha16A[NA * HH];
__device__ __half g_ha16B[NA * HH];
__device__ __half g_hp16A[NP * HH];
__device__ __half g_hp16B[NP * HH];

__device__ int g_deg_ap[NA];
__device__ int g_rp_ap[NA + 1];
__device__ int g_cur_ap[NA];
__device__ int g_ct_ap[EMAX];

__device__ int g_deg_pa[NP];
__device__ int g_rp_pa[NP + 1];
__device__ int g_cur_pa[NP];
__device__ int g_ct_pa[EMAX];

__device__ int g_deg_pp[NP];
__device__ int g_rp_pp[NP + 1];
__device__ int g_cur_pp[NP];
__device__ int g_ct_pp[EMAX];

__device__ float g_x1_ap[NHOP * NA], g_w2_ap[NHOP * NA];
__device__ float g_x1_pa[NHOP * NP], g_w2_pa[NHOP * NP];
__device__ float g_x1_pp[NHOP * NP], g_w2_pp[NHOP * NP];
// target-side scalars, DOUBLE-BUFFERED: hop i reads bank i&1, writes bank (i+1)&1
__device__ float g_h1_ap[2][NP], g_h1_pa[2][NA], g_h1_pp[2][NP];

// ------------------------- input projection GEMM (tensor cores) --------------
__global__ void __launch_bounds__(256) proj_tc_kernel(
        const float* __restrict__ Aa, const float* __restrict__ Wa,
        const float* __restrict__ ba, float* __restrict__ Ca,
        __half2* __restrict__ C16a, int Ma, int Ka, int nblkA,
        const float* __restrict__ Ap, const float* __restrict__ Wp,
        const float* __restrict__ bp, float* __restrict__ Cp,
        __half2* __restrict__ C16p, int Mp, int Kp) {
    const float* A; const float* W; const float* b; float* C; __half2* C16;
    int M, K, rowBase;
    if ((int)blockIdx.x < nblkA) {
        A = Aa; W = Wa; b = ba; C = Ca; C16 = C16a; M = Ma; K = Ka;
        rowBase = blockIdx.x * 64;
    } else {
        A = Ap; W = Wp; b = bp; C = Cp; C16 = C16p; M = Mp; K = Kp;
        rowBase = (blockIdx.x - nblkA) * 64;
    }

    __shared__ __align__(16) __nv_bfloat16 AsHi[64][24];
    __shared__ __align__(16) __nv_bfloat16 AsLo[64][24];
    __shared__ __align__(16) __nv_bfloat16 WsHi[16][72];
    __shared__ __align__(16) __nv_bfloat16 WsLo[16][72];
    __shared__ __align__(16) float Outs[64][68];
    __shared__ float bs[64];

    int tid = threadIdx.x;
    int wid = tid >> 5;
    int wr = wid >> 1;
    int wc = wid & 1;

    if (tid < 64) bs[tid] = b[tid];

    wmma::fragment<wmma::accumulator, 16, 16, 16, float> acc[2];
    wmma::fill_fragment(acc[0], 0.f);
    wmma::fill_fragment(acc[1], 0.f);

    int nk = K >> 4;
    for (int ks = 0; ks < nk; ks++) {
        int k0 = ks << 4;
        {
            int row = tid >> 2;
            int q = (tid & 3) * 4;
            float4 v = make_float4(0.f, 0.f, 0.f, 0.f);
            int gr = rowBase + row;
            if (gr < M) v = *reinterpret_cast<const float4*>(&A[(size_t)gr * K + k0 + q]);
            float vv[4] = {v.x, v.y, v.z, v.w};
#pragma unroll
            for (int j = 0; j < 4; j++) {
                __nv_bfloat16 h = __float2bfloat16_rn(vv[j]);
                AsHi[row][q + j] = h;
                AsLo[row][q + j] = __float2bfloat16_rn(vv[j] - __bfloat162float(h));
            }
        }
        {
            int row = tid >> 4;
            int c = (tid & 15) * 4;
            float4 v = *reinterpret_cast<const float4*>(&W[(size_t)(k0 + row) * 64 + c]);
            float vv[4] = {v.x, v.y, v.z, v.w};
#pragma unroll
            for (int j = 0; j < 4; j++) {
                __nv_bfloat16 h = __float2bfloat16_rn(vv[j]);
                WsHi[row][c + j] = h;
                WsLo[row][c + j] = __float2bfloat16_rn(vv[j] - __bfloat162float(h));
            }
        }
        __syncthreads();

        wmma::fragment<wmma::matrix_a, 16, 16, 16, __nv_bfloat16, wmma::row_major> aHi, aLo;
        wmma::load_matrix_sync(aHi, &AsHi[wr * 16][0], 24);
        wmma::load_matrix_sync(aLo, &AsLo[wr * 16][0], 24);
#pragma unroll
        for (int t = 0; t < 2; t++) {
            int c0 = wc * 32 + t * 16;
            wmma::fragment<wmma::matrix_b, 16, 16, 16, __nv_bfloat16, wmma::row_major> bHi, bLo;
            wmma::load_matrix_sync(bHi, &WsHi[0][c0], 72);
            wmma::load_matrix_sync(bLo, &WsLo[0][c0], 72);
            wmma::mma_sync(acc[t], aHi, bHi, acc[t]);
            wmma::mma_sync(acc[t], aLo, bHi, acc[t]);
            wmma::mma_sync(acc[t], aHi, bLo, acc[t]);
        }
        __syncthreads();
    }

#pragma unroll
    for (int t = 0; t < 2; t++)
        wmma::store_matrix_sync(&Outs[wr * 16][wc * 32 + t * 16], acc[t], 68,
                                wmma::mem_row_major);
    __syncthreads();

#pragma unroll
    for (int it = 0; it < 8; it++) {
        int p = tid + it * 256;
        int row = p >> 5;
        int c2 = (p & 31) * 2;
        int gr = rowBase + row;
        if (gr < M) {
            float v0 = Outs[row][c2] + bs[c2];
            float v1 = Outs[row][c2 + 1] + bs[c2 + 1];
            v0 = v0 > 0.f ? v0 : 0.f;
            v1 = v1 > 0.f ? v1 : 0.f;
            C[(size_t)gr * 64 + c2] = v0;
            C[(size_t)gr * 64 + c2 + 1] = v1;
            C16[(size_t)gr * 32 + (c2 >> 1)] = __floats2half2_rn(v0, v1);
        }
    }
}

// ------------------------- CSR build ----------------------------------------
__global__ void zero_deg_kernel() {
    int i = blockIdx.x * blockDim.x + threadIdx.x;
    if (i < NA) g_deg_ap[i] = 0;
    if (i < NP) { g_deg_pa[i] = 0; g_deg_pp[i] = 0; }
}

__global__ void hist_all_kernel(const int* __restrict__ s_ap, const int* __restrict__ s_pa,
                                const int* __restrict__ s_pp, int Eap, int Epa, int Epp) {
    int i = blockIdx.x * blockDim.x + threadIdx.x;
    int tot = Eap + Epa + Epp;
    if (i >= tot) return;
    if (i < Eap) atomicAdd(&g_deg_ap[s_ap[i]], 1);
    else if (i < Eap + Epa) atomicAdd(&g_deg_pa[s_pa[i - Eap]], 1);
    else atomicAdd(&g_deg_pp[s_pp[i - Eap - Epa]], 1);
}

__device__ void scan_block(const int* __restrict__ deg, int* __restrict__ rp,
                           int* __restrict__ cur, int n) {
    __shared__ int carry;
    __shared__ int wsum[32];
    if (threadIdx.x == 0) carry = 0;
    __syncthreads();
    int lane = threadIdx.x & 31, wid = threadIdx.x >> 5;
    for (int base = 0; base < n; base += 1024) {
        int i = base + threadIdx.x;
        int v = (i < n) ? deg[i] : 0;
        int x = v;
#pragma unroll
        for (int o = 1; o < 32; o <<= 1) {
            int y = __shfl_up_sync(0xffffffffu, x, o);
            if (lane >= o) x += y;
        }
        if (lane == 31) wsum[wid] = x;
        __syncthreads();
        if (wid == 0) {
            int sv = wsum[lane];
#pragma unroll
            for (int o = 1; o < 32; o <<= 1) {
                int y = __shfl_up_sync(0xffffffffu, sv, o);
                if (lane >= o) sv += y;
            }
            wsum[lane] = sv;
        }
        __syncthreads();
        int excl = carry + x - v + ((wid > 0) ? wsum[wid - 1] : 0);
        if (i < n) { rp[i] = excl; cur[i] = excl; }
        int tot = wsum[31];
        __syncthreads();
        if (threadIdx.x == 0) carry += tot;
        __syncthreads();
    }
    if (threadIdx.x == 0) rp[n] = carry;
}

__global__ void scan_all_kernel() {
    if (blockIdx.x == 0) scan_block(g_deg_ap, g_rp_ap, g_cur_ap, NA);
    else if (blockIdx.x == 1) scan_block(g_deg_pa, g_rp_pa, g_cur_pa, NP);
    else scan_block(g_deg_pp, g_rp_pp, g_cur_pp, NP);
}

__global__ void scatter_all_kernel(const int* __restrict__ s_ap, const int* __restrict__ t_ap,
                                   const int* __restrict__ s_pa, const int* __restrict__ t_pa,
                                   const int* __restrict__ s_pp, const int* __restrict__ t_pp,
                                   int Eap, int Epa, int Epp) {
    int i = blockIdx.x * blockDim.x + threadIdx.x;
    int tot = Eap + Epa + Epp;
    if (i >= tot) return;
    if (i < Eap) {
        int pos = atomicAdd(&g_cur_ap[s_ap[i]], 1);
        g_ct_ap[pos] = t_ap[i];
    } else if (i < Eap + Epa) {
        int j = i - Eap;
        int pos = atomicAdd(&g_cur_pa[s_pa[j]], 1);
        g_ct_pa[pos] = t_pa[j];
    } else {
        int j = i - Eap - Epa;
        int pos = atomicAdd(&g_cur_pp[s_pp[j]], 1);
        g_ct_pp[pos] = t_pp[j];
    }
}

// ------------------------- scalar precompute ---------------------------------
__device__ __forceinline__ float warp_red(float s) {
#pragma unroll
    for (int o = 16; o; o >>= 1) s += __shfl_xor_sync(0xffffffffu, s, o);
    return s;
}

__device__ __forceinline__ float half_red(float s) {
#pragma unroll
    for (int o = 8; o; o >>= 1) s += __shfl_xor_sync(0xffffffffu, s, o);
    return s;
}

__global__ void src_all_kernel(const float* __restrict__ xa, const float* __restrict__ xp,
                               const float* __restrict__ a1ap, const float* __restrict__ a2ap,
                               const float* __restrict__ a1pa, const float* __restrict__ a2pa,
                               const float* __restrict__ a1pp, const float* __restrict__ a2pp) {
    int w = (blockIdx.x * blockDim.x + threadIdx.x) >> 5;
    int lane = threadIdx.x & 31;
    if (w < NA) {
        const float* xr = xa + (size_t)w * HH;
        float v0 = xr[lane], v1 = xr[lane + 32];
#pragma unroll
        for (int i = 0; i < NHOP; i++) {
            float s1 = warp_red(v0 * a1ap[i * HH + lane] + v1 * a1ap[i * HH + lane + 32]);
            float s2 = warp_red(v0 * a2ap[i * HH + lane] + v1 * a2ap[i * HH + lane + 32]);
            if (lane == 0) {
                g_x1_ap[i * NA + w] = s1;
                float z = s1 + s2;
                z = z >= 0.f ? z : 0.2f * z;
                g_w2_ap[i * NA + w] = __expf(z);
            }
        }
    } else if (w < NA + NP) {
        int n = w - NA;
        const float* xr = xp + (size_t)n * HH;
        float v0 = xr[lane], v1 = xr[lane + 32];
#pragma unroll
        for (int i = 0; i < NHOP; i++) {
            float s1 = warp_red(v0 * a1pa[i * HH + lane] + v1 * a1pa[i * HH + lane + 32]);
            float s2 = warp_red(v0 * a2pa[i * HH + lane] + v1 * a2pa[i * HH + lane + 32]);
            float s3 = warp_red(v0 * a1pp[i * HH + lane] + v1 * a1pp[i * HH + lane + 32]);
            float s4 = warp_red(v0 * a2pp[i * HH + lane] + v1 * a2pp[i * HH + lane + 32]);
            if (lane == 0) {
                g_x1_pa[i * NP + n] = s1;
                float z = s1 + s2;
                z = z >= 0.f ? z : 0.2f * z;
                g_w2_pa[i * NP + n] = __expf(z);
                g_x1_pp[i * NP + n] = s3;
                float z2 = s3 + s4;
                z2 = z2 >= 0.f ? z2 : 0.2f * z2;
                g_w2_pp[i * NP + n] = __expf(z2);
            }
        }
    }
}

// hop-0 target scalars (writes bank 0; runs overlapped with CSR build)
__global__ void tgt_all_kernel(const __half2* __restrict__ ha16,
                               const __half2* __restrict__ hp16,
                               const float* __restrict__ a2ap,
                               const float* __restrict__ a2pa,
                               const float* __restrict__ a2pp) {
    int w = (blockIdx.x * blockDim.x + threadIdx.x) >> 5;
    int lane = threadIdx.x & 31;
    if (w < NP) {
        float2 f = __half22float2(hp16[(size_t)w * 32 + lane]);
        float s1 = warp_red(f.x * a2ap[2 * lane] + f.y * a2ap[2 * lane + 1]);
        float s2 = warp_red(f.x * a2pp[2 * lane] + f.y * a2pp[2 * lane + 1]);
        if (lane == 0) { g_h1_ap[0][w] = s1; g_h1_pp[0][w] = s2; }
    } else if (w < NP + NA) {
        int n = w - NP;
        float2 f = __half22float2(ha16[(size_t)n * 32 + lane]);
        float s = warp_red(f.x * a2pa[2 * lane] + f.y * a2pa[2 * lane + 1]);
        if (lane == 0) g_h1_pa[0][n] = s;
    }
}

// ------------------------- aggregation --------------------------------------
__device__ __forceinline__ float eluf(float v) { return v > 0.f ? v : (__expf(v) - 1.f); }

// 2 edge rows per warp-LDG; weight phase software-pipelined: next block's
// ct[jn] AND dependent h1[tn] are prefetched at iteration top so their ~2x262
// cycle serial chain retires under the current block's gather phase.
__device__ __forceinline__ void agg_rel16(int lane, int lane16, int hi,
                                          int beg, int end,
                                          const int* __restrict__ ct,
                                          const uint2* __restrict__ ht4,
                                          float x1s, const float* __restrict__ h1,
                                          float& wsum, float acc[4]) {
    float a0[4] = {0, 0, 0, 0}, a1[4] = {0, 0, 0, 0};
    float a2[4] = {0, 0, 0, 0}, a3[4] = {0, 0, 0, 0};
    // preload block 0's ct + h1
    int t = 0;
    float h1v = 0.f;
    {
        int j = beg + lane;
        if (j < end) { t = ct[j]; h1v = h1[t]; }
    }
    for (int j0 = beg; j0 < end; j0 += 32) {
        // prefetch next block (loads overlap with this block's gather phase)
        int jn = j0 + 32 + lane;
        int tn = 0;
        float h1n = 0.f;
        if (jn < end) tn = ct[jn];
        float wv = 0.f;
        if (j0 + lane < end) {
            float z = x1s + h1v;
            z = z >= 0.f ? z : 0.2f * z;
            wv = __expf(z);
            wsum += wv;
        }
        if (jn < end) h1n = h1[tn];
        int cnt = min(32, end - j0);
        int ng = (cnt + 7) >> 3;
        for (int g = 0; g < ng; g++) {
            int kb = (g << 3) + hi;
            int t0 = __shfl_sync(0xffffffffu, t, kb);
            int t1 = __shfl_sync(0xffffffffu, t, kb + 2);
            int t2 = __shfl_sync(0xffffffffu, t, kb + 4);
            int t3 = __shfl_sync(0xffffffffu, t, kb + 6);
            float w0 = __shfl_sync(0xffffffffu, wv, kb);
            float w1 = __shfl_sync(0xffffffffu, wv, kb + 2);
            float w2 = __shfl_sync(0xffffffffu, wv, kb + 4);
            float w3 = __shfl_sync(0xffffffffu, wv, kb + 6);
            uint2 v0 = ht4[(size_t)t0 * 16 + lane16];
            uint2 v1 = ht4[(size_t)t1 * 16 + lane16];
            uint2 v2 = ht4[(size_t)t2 * 16 + lane16];
            uint2 v3 = ht4[(size_t)t3 * 16 + lane16];
            {
                float2 lo = __half22float2(*reinterpret_cast<__half2*>(&v0.x));
                float2 hi2 = __half22float2(*reinterpret_cast<__half2*>(&v0.y));
                a0[0] += w0 * lo.x; a0[1] += w0 * lo.y; a0[2] += w0 * hi2.x; a0[3] += w0 * hi2.y;
            }
            {
                float2 lo = __half22float2(*reinterpret_cast<__half2*>(&v1.x));
                float2 hi2 = __half22float2(*reinterpret_cast<__half2*>(&v1.y));
                a1[0] += w1 * lo.x; a1[1] += w1 * lo.y; a1[2] += w1 * hi2.x; a1[3] += w1 * hi2.y;
            }
            {
                float2 lo = __half22float2(*reinterpret_cast<__half2*>(&v2.x));
                float2 hi2 = __half22float2(*reinterpret_cast<__half2*>(&v2.y));
                a2[0] += w2 * lo.x; a2[1] += w2 * lo.y; a2[2] += w2 * hi2.x; a2[3] += w2 * hi2.y;
            }
            {
                float2 lo = __half22float2(*reinterpret_cast<__half2*>(&v3.x));
                float2 hi2 = __half22float2(*reinterpret_cast<__half2*>(&v3.y));
                a3[0] += w3 * lo.x; a3[1] += w3 * lo.y; a3[2] += w3 * hi2.x; a3[3] += w3 * hi2.y;
            }
        }
        t = tn;
        h1v = h1n;
    }
#pragma unroll
    for (int d = 0; d < 4; d++) {
        float s = (a0[d] + a1[d]) + (a2[d] + a3[d]);
        s += __shfl_xor_sync(0xffffffffu, s, 16);
        acc[d] = s;
    }
}

__device__ __forceinline__ uint2 pack4(float o0, float o1, float o2, float o3) {
    uint2 r;
    __half2 p0 = __floats2half2_rn(o0, o1);
    __half2 p1 = __floats2half2_rn(o2, o3);
    r.x = *reinterpret_cast<unsigned int*>(&p0);
    r.y = *reinterpret_cast<unsigned int*>(&p1);
    return r;
}

// Merged per-hop aggregation with fused next-hop target scalars (double-buffered).
__global__ void __launch_bounds__(256) agg_all_kernel(
        const int* __restrict__ rp_ap, const int* __restrict__ ct_ap,
        const int* __restrict__ rp_pa, const int* __restrict__ ct_pa,
        const int* __restrict__ rp_pp, const int* __restrict__ ct_pp,
        const float* __restrict__ xa, const float* __restrict__ xp,
        const uint2* __restrict__ ha, const uint2* __restrict__ hp,
        const float* __restrict__ x1_ap, const float* __restrict__ w2_ap,
        const float* __restrict__ x1_pa, const float* __restrict__ w2_pa,
        const float* __restrict__ x1_pp, const float* __restrict__ w2_pp,
        uint2* __restrict__ hao, uint2* __restrict__ hpo,
        int rb, int wb, int has_next,
        const float* __restrict__ a2ap_n, const float* __restrict__ a2pa_n,
        const float* __restrict__ a2pp_n) {
    int wrp = (blockIdx.x * blockDim.x + threadIdx.x) >> 5;
    int lane = threadIdx.x & 31;
    int lane16 = lane & 15, hi = lane >> 4;
    int d0 = 4 * lane16;

    if (wrp < NA) {
        float x1s = x1_ap[wrp];
        float wsum = 0.f;
        float acc[4];
        agg_rel16(lane, lane16, hi, rp_ap[wrp], rp_ap[wrp + 1], ct_ap, hp,
                  x1s, g_h1_ap[rb], wsum, acc);
        wsum = warp_red(wsum);
        float w2s = w2_ap[wrp];
        float inv = 1.f / (wsum + w2s);
        float4 xv = reinterpret_cast<const float4*>(xa)[(size_t)wrp * 16 + lane16];
        float o0 = eluf((acc[0] + w2s * xv.x) * inv);
        float o1 = eluf((acc[1] + w2s * xv.y) * inv);
        float o2 = eluf((acc[2] + w2s * xv.z) * inv);
        float o3 = eluf((acc[3] + w2s * xv.w) * inv);
        if (hi == 0)
            hao[(size_t)wrp * 16 + lane16] = pack4(o0, o1, o2, o3);
        if (has_next) {
            float p = o0 * a2pa_n[d0] + o1 * a2pa_n[d0 + 1]
                    + o2 * a2pa_n[d0 + 2] + o3 * a2pa_n[d0 + 3];
            p = half_red(p);
            if (lane == 0) g_h1_pa[wb][wrp] = p;
        }
    } else if (wrp < NA + NP) {
        int n = wrp - NA;
        float ws1 = 0.f;
        float accA[4];
        agg_rel16(lane, lane16, hi, rp_pa[n], rp_pa[n + 1], ct_pa, ha,
                  x1_pa[n], g_h1_pa[rb], ws1, accA);
        ws1 = warp_red(ws1);

        float ws2 = 0.f;
        float accB[4];
        agg_rel16(lane, lane16, hi, rp_pp[n], rp_pp[n + 1], ct_pp, hp,
                  x1_pp[n], g_h1_pp[rb], ws2, accB);
        ws2 = warp_red(ws2);

        float w2a = w2_pa[n];
        float w2b = w2_pp[n];
        float inv1 = 1.f / (ws1 + w2a);
        float inv2 = 1.f / (ws2 + w2b);
        float4 xv = reinterpret_cast<const float4*>(xp)[(size_t)n * 16 + lane16];
        float o0 = eluf(0.5f * ((accA[0] + w2a * xv.x) * inv1 + (accB[0] + w2b * xv.x) * inv2));
        float o1 = eluf(0.5f * ((accA[1] + w2a * xv.y) * inv1 + (accB[1] + w2b * xv.y) * inv2));
        float o2 = eluf(0.5f * ((accA[2] + w2a * xv.z) * inv1 + (accB[2] + w2b * xv.z) * inv2));
        float o3 = eluf(0.5f * ((accA[3] + w2a * xv.w) * inv1 + (accB[3] + w2b * xv.w) * inv2));
        if (hi == 0)
            hpo[(size_t)n * 16 + lane16] = pack4(o0, o1, o2, o3);
        if (has_next) {
            float p1 = o0 * a2ap_n[d0] + o1 * a2ap_n[d0 + 1]
                     + o2 * a2ap_n[d0 + 2] + o3 * a2ap_n[d0 + 3];
            float p2 = o0 * a2pp_n[d0] + o1 * a2pp_n[d0 + 1]
                     + o2 * a2pp_n[d0 + 2] + o3 * a2pp_n[d0 + 3];
            p1 = half_red(p1);
            p2 = half_red(p2);
            if (lane == 0) { g_h1_ap[wb][n] = p1; g_h1_pp[wb][n] = p2; }
        }
    }
}

// ------------------------- output projection ---------------------------------
__global__ void fc2_kernel(const __half2* __restrict__ h, const float* __restrict__ W,
                           const float* __restrict__ b, float* __restrict__ out, int n) {
    __shared__ float Ws[HH * NOUT];
    __shared__ float bs[NOUT];
    for (int i = threadIdx.x; i < HH * NOUT; i += blockDim.x) Ws[i] = W[i];
    if (threadIdx.x < NOUT) bs[threadIdx.x] = b[threadIdx.x];
    __syncthreads();
    int idx = blockIdx.x * blockDim.x + threadIdx.x;
    int node = idx >> 4, col = idx & 15;
    if (node >= n) return;
    const __half2* hr = h + (size_t)node * 32;
    float s = bs[col];
#pragma unroll
    for (int k = 0; k < 32; k++) {
        float2 f = __half22float2(hr[k]);
        s += f.x * Ws[(2 * k) * NOUT + col] + f.y * Ws[(2 * k + 1) * NOUT + col];
    }
    out[(size_t)node * NOUT + col] = s;
}

// ------------------------- host orchestration --------------------------------
extern "C" void kernel_launch(void* const* d_in, const int* in_sizes, int n_in,
                              void* d_out, int out_size) {
    const float* x_a = (const float*)d_in[0];
    const float* x_p = (const float*)d_in[1];
    const int* ap_s = (const int*)d_in[2];
    const int* ap_t = (const int*)d_in[3];
    const int* pa_s = (const int*)d_in[4];
    const int* pa_t = (const int*)d_in[5];
    const int* pp_s = (const int*)d_in[6];
    const int* pp_t = (const int*)d_in[7];
    const float* fc1_a_w = (const float*)d_in[8];
    const float* fc1_a_b = (const float*)d_in[9];
    const float* fc1_p_w = (const float*)d_in[10];
    const float* fc1_p_b = (const float*)d_in[11];
    const float* fc2_w = (const float*)d_in[12];
    const float* fc2_b = (const float*)d_in[13];
    const float* a1_ap = (const float*)d_in[14];
    const float* a2_ap = (const float*)d_in[15];
    const float* a1_pa = (const float*)d_in[16];
    const float* a2_pa = (const float*)d_in[17];
    const float* a1_pp = (const float*)d_in[18];
    const float* a2_pp = (const float*)d_in[19];
    float* out = (float*)d_out;

    int E_ap = in_sizes[2], E_pa = in_sizes[4], E_pp = in_sizes[6];
    if (E_ap > EMAX) E_ap = EMAX;
    if (E_pa > EMAX) E_pa = EMAX;
    if (E_pp > EMAX) E_pp = EMAX;
    int E_tot = E_ap + E_pa + E_pp;

    float *xa, *xp;
    cudaGetSymbolAddress((void**)&xa, g_xa);
    cudaGetSymbolAddress((void**)&xp, g_xp);
    uint2 *ha16A, *ha16B, *hp16A, *hp16B;
    cudaGetSymbolAddress((void**)&ha16A, g_ha16A);
    cudaGetSymbolAddress((void**)&ha16B, g_ha16B);
    cudaGetSymbolAddress((void**)&hp16A, g_hp16A);
    cudaGetSymbolAddress((void**)&hp16B, g_hp16B);

    int *rp_ap, *ct_ap, *rp_pa, *ct_pa, *rp_pp, *ct_pp;
    cudaGetSymbolAddress((void**)&rp_ap, g_rp_ap);
    cudaGetSymbolAddress((void**)&ct_ap, g_ct_ap);
    cudaGetSymbolAddress((void**)&rp_pa, g_rp_pa);
    cudaGetSymbolAddress((void**)&ct_pa, g_ct_pa);
    cudaGetSymbolAddress((void**)&rp_pp, g_rp_pp);
    cudaGetSymbolAddress((void**)&ct_pp, g_ct_pp);

    float *x1_ap, *w2_ap, *x1_pa, *w2_pa, *x1_pp, *w2_pp;
    cudaGetSymbolAddress((void**)&x1_ap, g_x1_ap);
    cudaGetSymbolAddress((void**)&w2_ap, g_w2_ap);
    cudaGetSymbolAddress((void**)&x1_pa, g_x1_pa);
    cudaGetSymbolAddress((void**)&w2_pa, g_w2_pa);
    cudaGetSymbolAddress((void**)&x1_pp, g_x1_pp);
    cudaGetSymbolAddress((void**)&w2_pp, g_w2_pp);

    // --- forked-stream section: CSR build (stream 0) || proj chain (sB) ---
    cudaStream_t sB;
    cudaStreamCreateWithFlags(&sB, cudaStreamNonBlocking);
    cudaEvent_t eFork, eJoin;
    cudaEventCreateWithFlags(&eFork, cudaEventDisableTiming);
    cudaEventCreateWithFlags(&eJoin, cudaEventDisableTiming);

    cudaEventRecord(eFork, 0);
    cudaStreamWaitEvent(sB, eFork, 0);

    // Branch A (stream 0): CSR build
    zero_deg_kernel<<<(NP + 255) / 256, 256>>>();
    hist_all_kernel<<<(E_tot + 255) / 256, 256>>>(ap_s, pa_s, pp_s, E_ap, E_pa, E_pp);
    scan_all_kernel<<<3, 1024>>>();
    scatter_all_kernel<<<(E_tot + 255) / 256, 256>>>(ap_s, ap_t, pa_s, pa_t, pp_s, pp_t,
                                                     E_ap, E_pa, E_pp);

    // Branch B (sB): projections -> src scalars -> hop-0 tgt scalars (bank 0)
    int nblkA = (NA + 63) / 64;
    int nblkP = (NP + 63) / 64;
    proj_tc_kernel<<<nblkA + nblkP, 256, 0, sB>>>(
        x_a, fc1_a_w, fc1_a_b, xa, (__half2*)ha16A, NA, DA, nblkA,
        x_p, fc1_p_w, fc1_p_b, xp, (__half2*)hp16A, NP, DP);
    src_all_kernel<<<((NA + NP) * 32 + 255) / 256, 256, 0, sB>>>(
        xa, xp, a1_ap, a2_ap, a1_pa, a2_pa, a1_pp, a2_pp);
    tgt_all_kernel<<<((NP + NA) * 32 + 255) / 256, 256, 0, sB>>>(
        (const __half2*)ha16A, (const __half2*)hp16A, a2_ap, a2_pa, a2_pp);

    // Join
    cudaEventRecord(eJoin, sB);
    cudaStreamWaitEvent(0, eJoin, 0);

    // --- hops; h1 double-buffered (read i&1, write (i+1)&1) ---
    const uint2* ha = ha16A;
    const uint2* hp = hp16A;
    for (int i = 0; i < NHOP; i++) {
        uint2* hao = (i & 1) ? ha16A : ha16B;
        uint2* hpo = (i & 1) ? hp16A : hp16B;
        int has_next = (i + 1 < NHOP) ? 1 : 0;
        int nx = has_next ? (i + 1) : i;

        agg_all_kernel<<<((NA + NP) * 32 + 255) / 256, 256>>>(
            rp_ap, ct_ap, rp_pa, ct_pa, rp_pp, ct_pp, xa, xp, ha, hp,
            x1_ap + i * NA, w2_ap + i * NA,
            x1_pa + i * NP, w2_pa + i * NP,
            x1_pp + i * NP, w2_pp + i * NP,
            hao, hpo,
            i & 1, (i + 1) & 1,
            has_next, a2_ap + nx * HH, a2_pa + nx * HH, a2_pp + nx * HH);
        ha = hao;
        hp = hpo;
    }

    // output projection
    fc2_kernel<<<(NA * NOUT + 255) / 256, 256>>>((const __half2*)ha, fc2_w, fc2_b, out, NA);

    cudaStreamDestroy(sB);
    cudaEventDestroy(eFork);
    cudaEventDestroy(eJoin);
}

// round 14
// speedup vs baseline: 1.0145x; 1.0145x over previous
#include <cuda_runtime.h>
#include <cuda_fp16.h>
#include <cuda_bf16.h>
#include <mma.h>
#include <cstdint>

using namespace nvcuda;

#define NA 50000
#define NP 100000
#define DA 512
#define DP 256
#define HH 64
#define NOUT 16
#define NHOP 3
#define EMAX 2000000

// ------------------------- device scratch (static; no allocs) ----------------
__device__ float g_xa[NA * HH];
__device__ float g_xp[NP * HH];
__device__ __half g_ha16A[NA * HH];
__device__ __half g_ha16B[NA * HH];
__device__ __half g_hp16A[NP * HH];
__device__ __half g_hp16B[NP * HH];

__device__ int g_deg_ap[NA];
__device__ int g_rp_ap[NA + 1];
__device__ int g_cur_ap[NA];
__device__ int g_ct_ap[EMAX];

__device__ int g_deg_pa[NP];
__device__ int g_rp_pa[NP + 1];
__device__ int g_cur_pa[NP];
__device__ int g_ct_pa[EMAX];

__device__ int g_deg_pp[NP];
__device__ int g_rp_pp[NP + 1];
__device__ int g_cur_pp[NP];
__device__ int g_ct_pp[EMAX];

__device__ float g_x1_ap[NHOP * NA], g_w2_ap[NHOP * NA];
__device__ float g_x1_pa[NHOP * NP], g_w2_pa[NHOP * NP];
__device__ float g_x1_pp[NHOP * NP], g_w2_pp[NHOP * NP];
// target-side scalars, DOUBLE-BUFFERED: hop i reads bank i&1, writes bank (i+1)&1
__device__ float g_h1_ap[2][NP], g_h1_pa[2][NA], g_h1_pp[2][NP];

// ------------------------- input projection GEMM (tensor cores) --------------
__global__ void __launch_bounds__(256) proj_tc_kernel(
        const float* __restrict__ Aa, const float* __restrict__ Wa,
        const float* __restrict__ ba, float* __restrict__ Ca,
        __half2* __restrict__ C16a, int Ma, int Ka, int nblkA,
        const float* __restrict__ Ap, const float* __restrict__ Wp,
        const float* __restrict__ bp, float* __restrict__ Cp,
        __half2* __restrict__ C16p, int Mp, int Kp) {
    const float* A; const float* W; const float* b; float* C; __half2* C16;
    int M, K, rowBase;
    if ((int)blockIdx.x < nblkA) {
        A = Aa; W = Wa; b = ba; C = Ca; C16 = C16a; M = Ma; K = Ka;
        rowBase = blockIdx.x * 64;
    } else {
        A = Ap; W = Wp; b = bp; C = Cp; C16 = C16p; M = Mp; K = Kp;
        rowBase = (blockIdx.x - nblkA) * 64;
    }

    __shared__ __align__(16) __nv_bfloat16 AsHi[64][24];
    __shared__ __align__(16) __nv_bfloat16 AsLo[64][24];
    __shared__ __align__(16) __nv_bfloat16 WsHi[16][72];
    __shared__ __align__(16) __nv_bfloat16 WsLo[16][72];
    __shared__ __align__(16) float Outs[64][68];
    __shared__ float bs[64];

    int tid = threadIdx.x;
    int wid = tid >> 5;
    int wr = wid >> 1;
    int wc = wid & 1;

    if (tid < 64) bs[tid] = b[tid];

    wmma::fragment<wmma::accumulator, 16, 16, 16, float> acc[2];
    wmma::fill_fragment(acc[0], 0.f);
    wmma::fill_fragment(acc[1], 0.f);

    int nk = K >> 4;
    for (int ks = 0; ks < nk; ks++) {
        int k0 = ks << 4;
        {
            int row = tid >> 2;
            int q = (tid & 3) * 4;
            float4 v = make_float4(0.f, 0.f, 0.f, 0.f);
            int gr = rowBase + row;
            if (gr < M) v = *reinterpret_cast<const float4*>(&A[(size_t)gr * K + k0 + q]);
            float vv[4] = {v.x, v.y, v.z, v.w};
#pragma unroll
            for (int j = 0; j < 4; j++) {
                __nv_bfloat16 h = __float2bfloat16_rn(vv[j]);
                AsHi[row][q + j] = h;
                AsLo[row][q + j] = __float2bfloat16_rn(vv[j] - __bfloat162float(h));
            }
        }
        {
            int row = tid >> 4;
            int c = (tid & 15) * 4;
            float4 v = *reinterpret_cast<const float4*>(&W[(size_t)(k0 + row) * 64 + c]);
            float vv[4] = {v.x, v.y, v.z, v.w};
#pragma unroll
            for (int j = 0; j < 4; j++) {
                __nv_bfloat16 h = __float2bfloat16_rn(vv[j]);
                WsHi[row][c + j] = h;
                WsLo[row][c + j] = __float2bfloat16_rn(vv[j] - __bfloat162float(h));
            }
        }
        __syncthreads();

        wmma::fragment<wmma::matrix_a, 16, 16, 16, __nv_bfloat16, wmma::row_major> aHi, aLo;
        wmma::load_matrix_sync(aHi, &AsHi[wr * 16][0], 24);
        wmma::load_matrix_sync(aLo, &AsLo[wr * 16][0], 24);
#pragma unroll
        for (int t = 0; t < 2; t++) {
            int c0 = wc * 32 + t * 16;
            wmma::fragment<wmma::matrix_b, 16, 16, 16, __nv_bfloat16, wmma::row_major> bHi, bLo;
            wmma::load_matrix_sync(bHi, &WsHi[0][c0], 72);
            wmma::load_matrix_sync(bLo, &WsLo[0][c0], 72);
            wmma::mma_sync(acc[t], aHi, bHi, acc[t]);
            wmma::mma_sync(acc[t], aLo, bHi, acc[t]);
            wmma::mma_sync(acc[t], aHi, bLo, acc[t]);
        }
        __syncthreads();
    }

#pragma unroll
    for (int t = 0; t < 2; t++)
        wmma::store_matrix_sync(&Outs[wr * 16][wc * 32 + t * 16], acc[t], 68,
                                wmma::mem_row_major);
    __syncthreads();

#pragma unroll
    for (int it = 0; it < 8; it++) {
        int p = tid + it * 256;
        int row = p >> 5;
        int c2 = (p & 31) * 2;
        int gr = rowBase + row;
        if (gr < M) {
            float v0 = Outs[row][c2] + bs[c2];
            float v1 = Outs[row][c2 + 1] + bs[c2 + 1];
            v0 = v0 > 0.f ? v0 : 0.f;
            v1 = v1 > 0.f ? v1 : 0.f;
            C[(size_t)gr * 64 + c2] = v0;
            C[(size_t)gr * 64 + c2 + 1] = v1;
            C16[(size_t)gr * 32 + (c2 >> 1)] = __floats2half2_rn(v0, v1);
        }
    }
}

// ------------------------- CSR build ----------------------------------------
__global__ void zero_deg_kernel() {
    int i = blockIdx.x * blockDim.x + threadIdx.x;
    if (i < NA) g_deg_ap[i] = 0;
    if (i < NP) { g_deg_pa[i] = 0; g_deg_pp[i] = 0; }
}

__global__ void hist_all_kernel(const int* __restrict__ s_ap, const int* __restrict__ s_pa,
                                const int* __restrict__ s_pp, int Eap, int Epa, int Epp) {
    int i = blockIdx.x * blockDim.x + threadIdx.x;
    int tot = Eap + Epa + Epp;
    if (i >= tot) return;
    if (i < Eap) atomicAdd(&g_deg_ap[s_ap[i]], 1);
    else if (i < Eap + Epa) atomicAdd(&g_deg_pa[s_pa[i - Eap]], 1);
    else atomicAdd(&g_deg_pp[s_pp[i - Eap - Epa]], 1);
}

__device__ void scan_block(const int* __restrict__ deg, int* __restrict__ rp,
                           int* __restrict__ cur, int n) {
    __shared__ int carry;
    __shared__ int wsum[32];
    if (threadIdx.x == 0) carry = 0;
    __syncthreads();
    int lane = threadIdx.x & 31, wid = threadIdx.x >> 5;
    for (int base = 0; base < n; base += 1024) {
        int i = base + threadIdx.x;
        int v = (i < n) ? deg[i] : 0;
        int x = v;
#pragma unroll
        for (int o = 1; o < 32; o <<= 1) {
            int y = __shfl_up_sync(0xffffffffu, x, o);
            if (lane >= o) x += y;
        }
        if (lane == 31) wsum[wid] = x;
        __syncthreads();
        if (wid == 0) {
            int sv = wsum[lane];
#pragma unroll
            for (int o = 1; o < 32; o <<= 1) {
                int y = __shfl_up_sync(0xffffffffu, sv, o);
                if (lane >= o) sv += y;
            }
            wsum[lane] = sv;
        }
        __syncthreads();
        int excl = carry + x - v + ((wid > 0) ? wsum[wid - 1] : 0);
        if (i < n) { rp[i] = excl; cur[i] = excl; }
        int tot = wsum[31];
        __syncthreads();
        if (threadIdx.x == 0) carry += tot;
        __syncthreads();
    }
    if (threadIdx.x == 0) rp[n] = carry;
}

__global__ void scan_all_kernel() {
    if (blockIdx.x == 0) scan_block(g_deg_ap, g_rp_ap, g_cur_ap, NA);
    else if (blockIdx.x == 1) scan_block(g_deg_pa, g_rp_pa, g_cur_pa, NP);
    else scan_block(g_deg_pp, g_rp_pp, g_cur_pp, NP);
}

__global__ void scatter_all_kernel(const int* __restrict__ s_ap, const int* __restrict__ t_ap,
                                   const int* __restrict__ s_pa, const int* __restrict__ t_pa,
                                   const int* __restrict__ s_pp, const int* __restrict__ t_pp,
                                   int Eap, int Epa, int Epp) {
    int i = blockIdx.x * blockDim.x + threadIdx.x;
    int tot = Eap + Epa + Epp;
    if (i >= tot) return;
    if (i < Eap) {
        int pos = atomicAdd(&g_cur_ap[s_ap[i]], 1);
        g_ct_ap[pos] = t_ap[i];
    } else if (i < Eap + Epa) {
        int j = i - Eap;
        int pos = atomicAdd(&g_cur_pa[s_pa[j]], 1);
        g_ct_pa[pos] = t_pa[j];
    } else {
        int j = i - Eap - Epa;
        int pos = atomicAdd(&g_cur_pp[s_pp[j]], 1);
        g_ct_pp[pos] = t_pp[j];
    }
}

// ------------------------- scalar precompute ---------------------------------
__device__ __forceinline__ float warp_red(float s) {
#pragma unroll
    for (int o = 16; o; o >>= 1) s += __shfl_xor_sync(0xffffffffu, s, o);
    return s;
}

__device__ __forceinline__ float half_red(float s) {
#pragma unroll
    for (int o = 8; o; o >>= 1) s += __shfl_xor_sync(0xffffffffu, s, o);
    return s;
}

__global__ void src_all_kernel(const float* __restrict__ xa, const float* __restrict__ xp,
                               const float* __restrict__ a1ap, const float* __restrict__ a2ap,
                               const float* __restrict__ a1pa, const float* __restrict__ a2pa,
                               const float* __restrict__ a1pp, const float* __restrict__ a2pp) {
    int w = (blockIdx.x * blockDim.x + threadIdx.x) >> 5;
    int lane = threadIdx.x & 31;
    if (w < NA) {
        const float* xr = xa + (size_t)w * HH;
        float v0 = xr[lane], v1 = xr[lane + 32];
#pragma unroll
        for (int i = 0; i < NHOP; i++) {
            float s1 = warp_red(v0 * a1ap[i * HH + lane] + v1 * a1ap[i * HH + lane + 32]);
            float s2 = warp_red(v0 * a2ap[i * HH + lane] + v1 * a2ap[i * HH + lane + 32]);
            if (lane == 0) {
                g_x1_ap[i * NA + w] = s1;
                float z = s1 + s2;
                z = z >= 0.f ? z : 0.2f * z;
                g_w2_ap[i * NA + w] = __expf(z);
            }
        }
    } else if (w < NA + NP) {
        int n = w - NA;
        const float* xr = xp + (size_t)n * HH;
        float v0 = xr[lane], v1 = xr[lane + 32];
#pragma unroll
        for (int i = 0; i < NHOP; i++) {
            float s1 = warp_red(v0 * a1pa[i * HH + lane] + v1 * a1pa[i * HH + lane + 32]);
            float s2 = warp_red(v0 * a2pa[i * HH + lane] + v1 * a2pa[i * HH + lane + 32]);
            float s3 = warp_red(v0 * a1pp[i * HH + lane] + v1 * a1pp[i * HH + lane + 32]);
            float s4 = warp_red(v0 * a2pp[i * HH + lane] + v1 * a2pp[i * HH + lane + 32]);
            if (lane == 0) {
                g_x1_pa[i * NP + n] = s1;
                float z = s1 + s2;
                z = z >= 0.f ? z : 0.2f * z;
                g_w2_pa[i * NP + n] = __expf(z);
                g_x1_pp[i * NP + n] = s3;
                float z2 = s3 + s4;
                z2 = z2 >= 0.f ? z2 : 0.2f * z2;
                g_w2_pp[i * NP + n] = __expf(z2);
            }
        }
    }
}

// hop-0 target scalars (writes bank 0; runs overlapped with CSR build)
__global__ void tgt_all_kernel(const __half2* __restrict__ ha16,
                               const __half2* __restrict__ hp16,
                               const float* __restrict__ a2ap,
                               const float* __restrict__ a2pa,
                               const float* __restrict__ a2pp) {
    int w = (blockIdx.x * blockDim.x + threadIdx.x) >> 5;
    int lane = threadIdx.x & 31;
    if (w < NP) {
        float2 f = __half22float2(hp16[(size_t)w * 32 + lane]);
        float s1 = warp_red(f.x * a2ap[2 * lane] + f.y * a2ap[2 * lane + 1]);
        float s2 = warp_red(f.x * a2pp[2 * lane] + f.y * a2pp[2 * lane + 1]);
        if (lane == 0) { g_h1_ap[0][w] = s1; g_h1_pp[0][w] = s2; }
    } else if (w < NP + NA) {
        int n = w - NP;
        float2 f = __half22float2(ha16[(size_t)n * 32 + lane]);
        float s = warp_red(f.x * a2pa[2 * lane] + f.y * a2pa[2 * lane + 1]);
        if (lane == 0) g_h1_pa[0][n] = s;
    }
}

// ------------------------- aggregation --------------------------------------
__device__ __forceinline__ float eluf(float v) { return v > 0.f ? v : (__expf(v) - 1.f); }

// 2 edge rows per warp-LDG; weight phase software-pipelined: next block's
// ct[jn] AND dependent h1[tn] are prefetched at iteration top so their ~2x262
// cycle serial chain retires under the current block's gather phase.
__device__ __forceinline__ void agg_rel16(int lane, int lane16, int hi,
                                          int beg, int end,
                                          const int* __restrict__ ct,
                                          const uint2* __restrict__ ht4,
                                          float x1s, const float* __restrict__ h1,
                                          float& wsum, float acc[4]) {
    float a0[4] = {0, 0, 0, 0}, a1[4] = {0, 0, 0, 0};
    float a2[4] = {0, 0, 0, 0}, a3[4] = {0, 0, 0, 0};
    // preload block 0's ct + h1
    int t = 0;
    float h1v = 0.f;
    {
        int j = beg + lane;
        if (j < end) { t = ct[j]; h1v = h1[t]; }
    }
    for (int j0 = beg; j0 < end; j0 += 32) {
        // prefetch next block (loads overlap with this block's gather phase)
        int jn = j0 + 32 + lane;
        int tn = 0;
        float h1n = 0.f;
        if (jn < end) tn = ct[jn];
        float wv = 0.f;
        if (j0 + lane < end) {
            float z = x1s + h1v;
            z = z >= 0.f ? z : 0.2f * z;
            wv = __expf(z);
            wsum += wv;
        }
        if (jn < end) h1n = h1[tn];
        int cnt = min(32, end - j0);
        int ng = (cnt + 7) >> 3;
        for (int g = 0; g < ng; g++) {
            int kb = (g << 3) + hi;
            int t0 = __shfl_sync(0xffffffffu, t, kb);
            int t1 = __shfl_sync(0xffffffffu, t, kb + 2);
            int t2 = __shfl_sync(0xffffffffu, t, kb + 4);
            int t3 = __shfl_sync(0xffffffffu, t, kb + 6);
            float w0 = __shfl_sync(0xffffffffu, wv, kb);
            float w1 = __shfl_sync(0xffffffffu, wv, kb + 2);
            float w2 = __shfl_sync(0xffffffffu, wv, kb + 4);
            float w3 = __shfl_sync(0xffffffffu, wv, kb + 6);
            uint2 v0 = ht4[(size_t)t0 * 16 + lane16];
            uint2 v1 = ht4[(size_t)t1 * 16 + lane16];
            uint2 v2 = ht4[(size_t)t2 * 16 + lane16];
            uint2 v3 = ht4[(size_t)t3 * 16 + lane16];
            {
                float2 lo = __half22float2(*reinterpret_cast<__half2*>(&v0.x));
                float2 hi2 = __half22float2(*reinterpret_cast<__half2*>(&v0.y));
                a0[0] += w0 * lo.x; a0[1] += w0 * lo.y; a0[2] += w0 * hi2.x; a0[3] += w0 * hi2.y;
            }
            {
                float2 lo = __half22float2(*reinterpret_cast<__half2*>(&v1.x));
                float2 hi2 = __half22float2(*reinterpret_cast<__half2*>(&v1.y));
                a1[0] += w1 * lo.x; a1[1] += w1 * lo.y; a1[2] += w1 * hi2.x; a1[3] += w1 * hi2.y;
            }
            {
                float2 lo = __half22float2(*reinterpret_cast<__half2*>(&v2.x));
                float2 hi2 = __half22float2(*reinterpret_cast<__half2*>(&v2.y));
                a2[0] += w2 * lo.x; a2[1] += w2 * lo.y; a2[2] += w2 * hi2.x; a2[3] += w2 * hi2.y;
            }
            {
                float2 lo = __half22float2(*reinterpret_cast<__half2*>(&v3.x));
                float2 hi2 = __half22float2(*reinterpret_cast<__half2*>(&v3.y));
                a3[0] += w3 * lo.x; a3[1] += w3 * lo.y; a3[2] += w3 * hi2.x; a3[3] += w3 * hi2.y;
            }
        }
        t = tn;
        h1v = h1n;
    }
#pragma unroll
    for (int d = 0; d < 4; d++) {
        float s = (a0[d] + a1[d]) + (a2[d] + a3[d]);
        s += __shfl_xor_sync(0xffffffffu, s, 16);
        acc[d] = s;
    }
}

__device__ __forceinline__ uint2 pack4(float o0, float o1, float o2, float o3) {
    uint2 r;
    __half2 p0 = __floats2half2_rn(o0, o1);
    __half2 p1 = __floats2half2_rn(o2, o3);
    r.x = *reinterpret_cast<unsigned int*>(&p0);
    r.y = *reinterpret_cast<unsigned int*>(&p1);
    return r;
}

// Merged per-hop aggregation with fused next-hop target scalars (double-buffered).
__global__ void __launch_bounds__(256) agg_all_kernel(
        const int* __restrict__ rp_ap, const int* __restrict__ ct_ap,
        const int* __restrict__ rp_pa, const int* __restrict__ ct_pa,
        const int* __restrict__ rp_pp, const int* __restrict__ ct_pp,
        const float* __restrict__ xa, const float* __restrict__ xp,
        const uint2* __restrict__ ha, const uint2* __restrict__ hp,
        const float* __restrict__ x1_ap, const float* __restrict__ w2_ap,
        const float* __restrict__ x1_pa, const float* __restrict__ w2_pa,
        const float* __restrict__ x1_pp, const float* __restrict__ w2_pp,
        uint2* __restrict__ hao, uint2* __restrict__ hpo,
        int rb, int wb, int has_next,
        const float* __restrict__ a2ap_n, const float* __restrict__ a2pa_n,
        const float* __restrict__ a2pp_n) {
    int wrp = (blockIdx.x * blockDim.x + threadIdx.x) >> 5;
    int lane = threadIdx.x & 31;
    int lane16 = lane & 15, hi = lane >> 4;
    int d0 = 4 * lane16;

    if (wrp < NA) {
        float x1s = x1_ap[wrp];
        float wsum = 0.f;
        float acc[4];
        agg_rel16(lane, lane16, hi, rp_ap[wrp], rp_ap[wrp + 1], ct_ap, hp,
                  x1s, g_h1_ap[rb], wsum, acc);
        wsum = warp_red(wsum);
        float w2s = w2_ap[wrp];
        float inv = 1.f / (wsum + w2s);
        float4 xv = reinterpret_cast<const float4*>(xa)[(size_t)wrp * 16 + lane16];
        float o0 = eluf((acc[0] + w2s * xv.x) * inv);
        float o1 = eluf((acc[1] + w2s * xv.y) * inv);
        float o2 = eluf((acc[2] + w2s * xv.z) * inv);
        float o3 = eluf((acc[3] + w2s * xv.w) * inv);
        if (hi == 0)
            hao[(size_t)wrp * 16 + lane16] = pack4(o0, o1, o2, o3);
        if (has_next) {
            float p = o0 * a2pa_n[d0] + o1 * a2pa_n[d0 + 1]
                    + o2 * a2pa_n[d0 + 2] + o3 * a2pa_n[d0 + 3];
            p = half_red(p);
            if (lane == 0) g_h1_pa[wb][wrp] = p;
        }
    } else if (wrp < NA + NP) {
        int n = wrp - NA;
        float ws1 = 0.f;
        float accA[4];
        agg_rel16(lane, lane16, hi, rp_pa[n], rp_pa[n + 1], ct_pa, ha,
                  x1_pa[n], g_h1_pa[rb], ws1, accA);
        ws1 = warp_red(ws1);

        float ws2 = 0.f;
        float accB[4];
        agg_rel16(lane, lane16, hi, rp_pp[n], rp_pp[n + 1], ct_pp, hp,
                  x1_pp[n], g_h1_pp[rb], ws2, accB);
        ws2 = warp_red(ws2);

        float w2a = w2_pa[n];
        float w2b = w2_pp[n];
        float inv1 = 1.f / (ws1 + w2a);
        float inv2 = 1.f / (ws2 + w2b);
        float4 xv = reinterpret_cast<const float4*>(xp)[(size_t)n * 16 + lane16];
        float o0 = eluf(0.5f * ((accA[0] + w2a * xv.x) * inv1 + (accB[0] + w2b * xv.x) * inv2));
        float o1 = eluf(0.5f * ((accA[1] + w2a * xv.y) * inv1 + (accB[1] + w2b * xv.y) * inv2));
        float o2 = eluf(0.5f * ((accA[2] + w2a * xv.z) * inv1 + (accB[2] + w2b * xv.z) * inv2));
        float o3 = eluf(0.5f * ((accA[3] + w2a * xv.w) * inv1 + (accB[3] + w2b * xv.w) * inv2));
        if (hi == 0)
            hpo[(size_t)n * 16 + lane16] = pack4(o0, o1, o2, o3);
        if (has_next) {
            float p1 = o0 * a2ap_n[d0] + o1 * a2ap_n[d0 + 1]
                     + o2 * a2ap_n[d0 + 2] + o3 * a2ap_n[d0 + 3];
            float p2 = o0 * a2pp_n[d0] + o1 * a2pp_n[d0 + 1]
                     + o2 * a2pp_n[d0 + 2] + o3 * a2pp_n[d0 + 3];
            p1 = half_red(p1);
            p2 = half_red(p2);
            if (lane == 0) { g_h1_ap[wb][n] = p1; g_h1_pp[wb][n] = p2; }
        }
    }
}

// ------------------------- output projection ---------------------------------
__global__ void fc2_kernel(const __half2* __restrict__ h, const float* __restrict__ W,
                           const float* __restrict__ b, float* __restrict__ out, int n) {
    __shared__ float Ws[HH * NOUT];
    __shared__ float bs[NOUT];
    for (int i = threadIdx.x; i < HH * NOUT; i += blockDim.x) Ws[i] = W[i];
    if (threadIdx.x < NOUT) bs[threadIdx.x] = b[threadIdx.x];
    __syncthreads();
    int idx = blockIdx.x * blockDim.x + threadIdx.x;
    int node = idx >> 4, col = idx & 15;
    if (node >= n) return;
    const __half2* hr = h + (size_t)node * 32;
    float s = bs[col];
#pragma unroll
    for (int k = 0; k < 32; k++) {
        float2 f = __half22float2(hr[k]);
        s += f.x * Ws[(2 * k) * NOUT + col] + f.y * Ws[(2 * k + 1) * NOUT + col];
    }
    out[(size_t)node * NOUT + col] = s;
}

// ------------------------- host orchestration --------------------------------
extern "C" void kernel_launch(void* const* d_in, const int* in_sizes, int n_in,
                              void* d_out, int out_size) {
    const float* x_a = (const float*)d_in[0];
    const float* x_p = (const float*)d_in[1];
    const int* ap_s = (const int*)d_in[2];
    const int* ap_t = (const int*)d_in[3];
    const int* pa_s = (const int*)d_in[4];
    const int* pa_t = (const int*)d_in[5];
    const int* pp_s = (const int*)d_in[6];
    const int* pp_t = (const int*)d_in[7];
    const float* fc1_a_w = (const float*)d_in[8];
    const float* fc1_a_b = (const float*)d_in[9];
    const float* fc1_p_w = (const float*)d_in[10];
    const float* fc1_p_b = (const float*)d_in[11];
    const float* fc2_w = (const float*)d_in[12];
    const float* fc2_b = (const float*)d_in[13];
    const float* a1_ap = (const float*)d_in[14];
    const float* a2_ap = (const float*)d_in[15];
    const float* a1_pa = (const float*)d_in[16];
    const float* a2_pa = (const float*)d_in[17];
    const float* a1_pp = (const float*)d_in[18];
    const float* a2_pp = (const float*)d_in[19];
    float* out = (float*)d_out;

    int E_ap = in_sizes[2], E_pa = in_sizes[4], E_pp = in_sizes[6];
    if (E_ap > EMAX) E_ap = EMAX;
    if (E_pa > EMAX) E_pa = EMAX;
    if (E_pp > EMAX) E_pp = EMAX;
    int E_tot = E_ap + E_pa + E_pp;

    float *xa, *xp;
    cudaGetSymbolAddress((void**)&xa, g_xa);
    cudaGetSymbolAddress((void**)&xp, g_xp);
    uint2 *ha16A, *ha16B, *hp16A, *hp16B;
    cudaGetSymbolAddress((void**)&ha16A, g_ha16A);
    cudaGetSymbolAddress((void**)&ha16B, g_ha16B);
    cudaGetSymbolAddress((void**)&hp16A, g_hp16A);
    cudaGetSymbolAddress((void**)&hp16B, g_hp16B);

    int *rp_ap, *ct_ap, *rp_pa, *ct_pa, *rp_pp, *ct_pp;
    cudaGetSymbolAddress((void**)&rp_ap, g_rp_ap);
    cudaGetSymbolAddress((void**)&ct_ap, g_ct_ap);
    cudaGetSymbolAddress((void**)&rp_pa, g_rp_pa);
    cudaGetSymbolAddress((void**)&ct_pa, g_ct_pa);
    cudaGetSymbolAddress((void**)&rp_pp, g_rp_pp);
    cudaGetSymbolAddress((void**)&ct_pp, g_ct_pp);

    float *x1_ap, *w2_ap, *x1_pa, *w2_pa, *x1_pp, *w2_pp;
    cudaGetSymbolAddress((void**)&x1_ap, g_x1_ap);
    cudaGetSymbolAddress((void**)&w2_ap, g_w2_ap);
    cudaGetSymbolAddress((void**)&x1_pa, g_x1_pa);
    cudaGetSymbolAddress((void**)&w2_pa, g_w2_pa);
    cudaGetSymbolAddress((void**)&x1_pp, g_x1_pp);
    cudaGetSymbolAddress((void**)&w2_pp, g_w2_pp);

    // --- forked-stream section: CSR build (stream 0) || proj chain (sB) ---
    cudaStream_t sB;
    cudaStreamCreateWithFlags(&sB, cudaStreamNonBlocking);
    cudaEvent_t eFork, eJoin;
    cudaEventCreateWithFlags(&eFork, cudaEventDisableTiming);
    cudaEventCreateWithFlags(&eJoin, cudaEventDisableTiming);

    cudaEventRecord(eFork, 0);
    cudaStreamWaitEvent(sB, eFork, 0);

    // Branch A (stream 0): CSR build
    zero_deg_kernel<<<(NP + 255) / 256, 256>>>();
    hist_all_kernel<<<(E_tot + 255) / 256, 256>>>(ap_s, pa_s, pp_s, E_ap, E_pa, E_pp);
    scan_all_kernel<<<3, 1024>>>();
    scatter_all_kernel<<<(E_tot + 255) / 256, 256>>>(ap_s, ap_t, pa_s, pa_t, pp_s, pp_t,
                                                     E_ap, E_pa, E_pp);

    // Branch B (sB): projections -> src scalars -> hop-0 tgt scalars (bank 0)
    int nblkA = (NA + 63) / 64;
    int nblkP = (NP + 63) / 64;
    proj_tc_kernel<<<nblkA + nblkP, 256, 0, sB>>>(
        x_a, fc1_a_w, fc1_a_b, xa, (__half2*)ha16A, NA, DA, nblkA,
        x_p, fc1_p_w, fc1_p_b, xp, (__half2*)hp16A, NP, DP);
    src_all_kernel<<<((NA + NP) * 32 + 255) / 256, 256, 0, sB>>>(
        xa, xp, a1_ap, a2_ap, a1_pa, a2_pa, a1_pp, a2_pp);
    tgt_all_kernel<<<((NP + NA) * 32 + 255) / 256, 256, 0, sB>>>(
        (const __half2*)ha16A, (const __half2*)hp16A, a2_ap, a2_pa, a2_pp);

    // Join
    cudaEventRecord(eJoin, sB);
    cudaStreamWaitEvent(0, eJoin, 0);

    // --- hops; h1 double-buffered (read i&1, write (i+1)&1) ---
    const uint2* ha = ha16A;
    const uint2* hp = hp16A;
    for (int i = 0; i < NHOP; i++) {
        uint2* hao = (i & 1) ? ha16A : ha16B;
        uint2* hpo = (i & 1) ? hp16A : hp16B;
        int has_next = (i + 1 < NHOP) ? 1 : 0;
        int nx = has_next ? (i + 1) : i;

        agg_all_kernel<<<((NA + NP) * 32 + 255) / 256, 256>>>(
            rp_ap, ct_ap, rp_pa, ct_pa, rp_pp, ct_pp, xa, xp, ha, hp,
            x1_ap + i * NA, w2_ap + i * NA,
            x1_pa + i * NP, w2_pa + i * NP,
            x1_pp + i * NP, w2_pp + i * NP,
            hao, hpo,
            i & 1, (i + 1) & 1,
            has_next, a2_ap + nx * HH, a2_pa + nx * HH, a2_pp + nx * HH);
        ha = hao;
        hp = hpo;
    }

    // output projection
    fc2_kernel<<<(NA * NOUT + 255) / 256, 256>>>((const __half2*)ha, fc2_w, fc2_b, out, NA);

    cudaStreamDestroy(sB);
    cudaEventDestroy(eFork);
    cudaEventDestroy(eJoin);
}

// round 16
// speedup vs baseline: 1.0146x; 1.0001x over previous
#include <cuda_runtime.h>
#include <cuda_fp16.h>
#include <cuda_bf16.h>
#include <mma.h>
#include <cstdint>

using namespace nvcuda;

#define NA 50000
#define NP 100000
#define DA 512
#define DP 256
#define HH 64
#define NOUT 16
#define NHOP 3
#define EMAX 2000000

// ------------------------- device scratch (static; no allocs) ----------------
__device__ float g_xa[NA * HH];
__device__ float g_xp[NP * HH];
__device__ __half g_ha16A[NA * HH];
__device__ __half g_ha16B[NA * HH];
__device__ __half g_hp16A[NP * HH];
__device__ __half g_hp16B[NP * HH];

__device__ int g_deg_ap[NA];
__device__ int g_rp_ap[NA + 1];
__device__ int g_cur_ap[NA];
__device__ int g_ct_ap[EMAX];

__device__ int g_deg_pa[NP];
__device__ int g_rp_pa[NP + 1];
__device__ int g_cur_pa[NP];
__device__ int g_ct_pa[EMAX];

__device__ int g_deg_pp[NP];
__device__ int g_rp_pp[NP + 1];
__device__ int g_cur_pp[NP];
__device__ int g_ct_pp[EMAX];

__device__ float g_x1_ap[NHOP * NA], g_w2_ap[NHOP * NA];
__device__ float g_x1_pa[NHOP * NP], g_w2_pa[NHOP * NP];
__device__ float g_x1_pp[NHOP * NP], g_w2_pp[NHOP * NP];
// target-side scalars, DOUBLE-BUFFERED: hop i reads bank i&1, writes bank (i+1)&1
__device__ float g_h1_ap[2][NP], g_h1_pa[2][NA], g_h1_pp[2][NP];

// ------------------------- input projection GEMM (tensor cores) --------------
__global__ void __launch_bounds__(256) proj_tc_kernel(
        const float* __restrict__ Aa, const float* __restrict__ Wa,
        const float* __restrict__ ba, float* __restrict__ Ca,
        __half2* __restrict__ C16a, int Ma, int Ka, int nblkA,
        const float* __restrict__ Ap, const float* __restrict__ Wp,
        const float* __restrict__ bp, float* __restrict__ Cp,
        __half2* __restrict__ C16p, int Mp, int Kp) {
    const float* A; const float* W; const float* b; float* C; __half2* C16;
    int M, K, rowBase;
    if ((int)blockIdx.x < nblkA) {
        A = Aa; W = Wa; b = ba; C = Ca; C16 = C16a; M = Ma; K = Ka;
        rowBase = blockIdx.x * 64;
    } else {
        A = Ap; W = Wp; b = bp; C = Cp; C16 = C16p; M = Mp; K = Kp;
        rowBase = (blockIdx.x - nblkA) * 64;
    }

    __shared__ __align__(16) __nv_bfloat16 AsHi[64][24];
    __shared__ __align__(16) __nv_bfloat16 AsLo[64][24];
    __shared__ __align__(16) __nv_bfloat16 WsHi[16][72];
    __shared__ __align__(16) __nv_bfloat16 WsLo[16][72];
    __shared__ __align__(16) float Outs[64][68];
    __shared__ float bs[64];

    int tid = threadIdx.x;
    int wid = tid >> 5;
    int wr = wid >> 1;
    int wc = wid & 1;

    if (tid < 64) bs[tid] = b[tid];

    wmma::fragment<wmma::accumulator, 16, 16, 16, float> acc[2];
    wmma::fill_fragment(acc[0], 0.f);
    wmma::fill_fragment(acc[1], 0.f);

    int nk = K >> 4;
    for (int ks = 0; ks < nk; ks++) {
        int k0 = ks << 4;
        {
            int row = tid >> 2;
            int q = (tid & 3) * 4;
            float4 v = make_float4(0.f, 0.f, 0.f, 0.f);
            int gr = rowBase + row;
            if (gr < M) v = *reinterpret_cast<const float4*>(&A[(size_t)gr * K + k0 + q]);
            float vv[4] = {v.x, v.y, v.z, v.w};
#pragma unroll
            for (int j = 0; j < 4; j++) {
                __nv_bfloat16 h = __float2bfloat16_rn(vv[j]);
                AsHi[row][q + j] = h;
                AsLo[row][q + j] = __float2bfloat16_rn(vv[j] - __bfloat162float(h));
            }
        }
        {
            int row = tid >> 4;
            int c = (tid & 15) * 4;
            float4 v = *reinterpret_cast<const float4*>(&W[(size_t)(k0 + row) * 64 + c]);
            float vv[4] = {v.x, v.y, v.z, v.w};
#pragma unroll
            for (int j = 0; j < 4; j++) {
                __nv_bfloat16 h = __float2bfloat16_rn(vv[j]);
                WsHi[row][c + j] = h;
                WsLo[row][c + j] = __float2bfloat16_rn(vv[j] - __bfloat162float(h));
            }
        }
        __syncthreads();

        wmma::fragment<wmma::matrix_a, 16, 16, 16, __nv_bfloat16, wmma::row_major> aHi, aLo;
        wmma::load_matrix_sync(aHi, &AsHi[wr * 16][0], 24);
        wmma::load_matrix_sync(aLo, &AsLo[wr * 16][0], 24);
#pragma unroll
        for (int t = 0; t < 2; t++) {
            int c0 = wc * 32 + t * 16;
            wmma::fragment<wmma::matrix_b, 16, 16, 16, __nv_bfloat16, wmma::row_major> bHi, bLo;
            wmma::load_matrix_sync(bHi, &WsHi[0][c0], 72);
            wmma::load_matrix_sync(bLo, &WsLo[0][c0], 72);
            wmma::mma_sync(acc[t], aHi, bHi, acc[t]);
            wmma::mma_sync(acc[t], aLo, bHi, acc[t]);
            wmma::mma_sync(acc[t], aHi, bLo, acc[t]);
        }
        __syncthreads();
    }

#pragma unroll
    for (int t = 0; t < 2; t++)
        wmma::store_matrix_sync(&Outs[wr * 16][wc * 32 + t * 16], acc[t], 68,
                                wmma::mem_row_major);
    __syncthreads();

#pragma unroll
    for (int it = 0; it < 8; it++) {
        int p = tid + it * 256;
        int row = p >> 5;
        int c2 = (p & 31) * 2;
        int gr = rowBase + row;
        if (gr < M) {
            float v0 = Outs[row][c2] + bs[c2];
            float v1 = Outs[row][c2 + 1] + bs[c2 + 1];
            v0 = v0 > 0.f ? v0 : 0.f;
            v1 = v1 > 0.f ? v1 : 0.f;
            C[(size_t)gr * 64 + c2] = v0;
            C[(size_t)gr * 64 + c2 + 1] = v1;
            C16[(size_t)gr * 32 + (c2 >> 1)] = __floats2half2_rn(v0, v1);
        }
    }
}

// ------------------------- CSR build ----------------------------------------
__global__ void zero_deg_kernel() {
    int i = blockIdx.x * blockDim.x + threadIdx.x;
    if (i < NA) g_deg_ap[i] = 0;
    if (i < NP) { g_deg_pa[i] = 0; g_deg_pp[i] = 0; }
}

__global__ void hist_all_kernel(const int* __restrict__ s_ap, const int* __restrict__ s_pa,
                                const int* __restrict__ s_pp, int Eap, int Epa, int Epp) {
    int i = blockIdx.x * blockDim.x + threadIdx.x;
    int tot = Eap + Epa + Epp;
    if (i >= tot) return;
    if (i < Eap) atomicAdd(&g_deg_ap[s_ap[i]], 1);
    else if (i < Eap + Epa) atomicAdd(&g_deg_pa[s_pa[i - Eap]], 1);
    else atomicAdd(&g_deg_pp[s_pp[i - Eap - Epa]], 1);
}

__device__ void scan_block(const int* __restrict__ deg, int* __restrict__ rp,
                           int* __restrict__ cur, int n) {
    __shared__ int carry;
    __shared__ int wsum[32];
    if (threadIdx.x == 0) carry = 0;
    __syncthreads();
    int lane = threadIdx.x & 31, wid = threadIdx.x >> 5;
    for (int base = 0; base < n; base += 1024) {
        int i = base + threadIdx.x;
        int v = (i < n) ? deg[i] : 0;
        int x = v;
#pragma unroll
        for (int o = 1; o < 32; o <<= 1) {
            int y = __shfl_up_sync(0xffffffffu, x, o);
            if (lane >= o) x += y;
        }
        if (lane == 31) wsum[wid] = x;
        __syncthreads();
        if (wid == 0) {
            int sv = wsum[lane];
#pragma unroll
            for (int o = 1; o < 32; o <<= 1) {
                int y = __shfl_up_sync(0xffffffffu, sv, o);
                if (lane >= o) sv += y;
            }
            wsum[lane] = sv;
        }
        __syncthreads();
        int excl = carry + x - v + ((wid > 0) ? wsum[wid - 1] : 0);
        if (i < n) { rp[i] = excl; cur[i] = excl; }
        int tot = wsum[31];
        __syncthreads();
        if (threadIdx.x == 0) carry += tot;
        __syncthreads();
    }
    if (threadIdx.x == 0) rp[n] = carry;
}

__global__ void scan_all_kernel() {
    if (blockIdx.x == 0) scan_block(g_deg_ap, g_rp_ap, g_cur_ap, NA);
    else if (blockIdx.x == 1) scan_block(g_deg_pa, g_rp_pa, g_cur_pa, NP);
    else scan_block(g_deg_pp, g_rp_pp, g_cur_pp, NP);
}

__global__ void scatter_all_kernel(const int* __restrict__ s_ap, const int* __restrict__ t_ap,
                                   const int* __restrict__ s_pa, const int* __restrict__ t_pa,
                                   const int* __restrict__ s_pp, const int* __restrict__ t_pp,
                                   int Eap, int Epa, int Epp) {
    int i = blockIdx.x * blockDim.x + threadIdx.x;
    int tot = Eap + Epa + Epp;
    if (i >= tot) return;
    if (i < Eap) {
        int pos = atomicAdd(&g_cur_ap[s_ap[i]], 1);
        g_ct_ap[pos] = t_ap[i];
    } else if (i < Eap + Epa) {
        int j = i - Eap;
        int pos = atomicAdd(&g_cur_pa[s_pa[j]], 1);
        g_ct_pa[pos] = t_pa[j];
    } else {
        int j = i - Eap - Epa;
        int pos = atomicAdd(&g_cur_pp[s_pp[j]], 1);
        g_ct_pp[pos] = t_pp[j];
    }
}

// ------------------------- scalar precompute ---------------------------------
__device__ __forceinline__ float warp_red(float s) {
#pragma unroll
    for (int o = 16; o; o >>= 1) s += __shfl_xor_sync(0xffffffffu, s, o);
    return s;
}

__device__ __forceinline__ float half_red(float s) {
#pragma unroll
    for (int o = 8; o; o >>= 1) s += __shfl_xor_sync(0xffffffffu, s, o);
    return s;
}

__global__ void src_all_kernel(const float* __restrict__ xa, const float* __restrict__ xp,
                               const float* __restrict__ a1ap, const float* __restrict__ a2ap,
                               const float* __restrict__ a1pa, const float* __restrict__ a2pa,
                               const float* __restrict__ a1pp, const float* __restrict__ a2pp) {
    int w = (blockIdx.x * blockDim.x + threadIdx.x) >> 5;
    int lane = threadIdx.x & 31;
    if (w < NA) {
        const float* xr = xa + (size_t)w * HH;
        float v0 = xr[lane], v1 = xr[lane + 32];
#pragma unroll
        for (int i = 0; i < NHOP; i++) {
            float s1 = warp_red(v0 * a1ap[i * HH + lane] + v1 * a1ap[i * HH + lane + 32]);
            float s2 = warp_red(v0 * a2ap[i * HH + lane] + v1 * a2ap[i * HH + lane + 32]);
            if (lane == 0) {
                g_x1_ap[i * NA + w] = s1;
                float z = s1 + s2;
                z = z >= 0.f ? z : 0.2f * z;
                g_w2_ap[i * NA + w] = __expf(z);
            }
        }
    } else if (w < NA + NP) {
        int n = w - NA;
        const float* xr = xp + (size_t)n * HH;
        float v0 = xr[lane], v1 = xr[lane + 32];
#pragma unroll
        for (int i = 0; i < NHOP; i++) {
            float s1 = warp_red(v0 * a1pa[i * HH + lane] + v1 * a1pa[i * HH + lane + 32]);
            float s2 = warp_red(v0 * a2pa[i * HH + lane] + v1 * a2pa[i * HH + lane + 32]);
            float s3 = warp_red(v0 * a1pp[i * HH + lane] + v1 * a1pp[i * HH + lane + 32]);
            float s4 = warp_red(v0 * a2pp[i * HH + lane] + v1 * a2pp[i * HH + lane + 32]);
            if (lane == 0) {
                g_x1_pa[i * NP + n] = s1;
                float z = s1 + s2;
                z = z >= 0.f ? z : 0.2f * z;
                g_w2_pa[i * NP + n] = __expf(z);
                g_x1_pp[i * NP + n] = s3;
                float z2 = s3 + s4;
                z2 = z2 >= 0.f ? z2 : 0.2f * z2;
                g_w2_pp[i * NP + n] = __expf(z2);
            }
        }
    }
}

// hop-0 target scalars (writes bank 0; runs overlapped with CSR build)
__global__ void tgt_all_kernel(const __half2* __restrict__ ha16,
                               const __half2* __restrict__ hp16,
                               const float* __restrict__ a2ap,
                               const float* __restrict__ a2pa,
                               const float* __restrict__ a2pp) {
    int w = (blockIdx.x * blockDim.x + threadIdx.x) >> 5;
    int lane = threadIdx.x & 31;
    if (w < NP) {
        float2 f = __half22float2(hp16[(size_t)w * 32 + lane]);
        float s1 = warp_red(f.x * a2ap[2 * lane] + f.y * a2ap[2 * lane + 1]);
        float s2 = warp_red(f.x * a2pp[2 * lane] + f.y * a2pp[2 * lane + 1]);
        if (lane == 0) { g_h1_ap[0][w] = s1; g_h1_pp[0][w] = s2; }
    } else if (w < NP + NA) {
        int n = w - NP;
        float2 f = __half22float2(ha16[(size_t)n * 32 + lane]);
        float s = warp_red(f.x * a2pa[2 * lane] + f.y * a2pa[2 * lane + 1]);
        if (lane == 0) g_h1_pa[0][n] = s;
    }
}

// ------------------------- aggregation --------------------------------------
__device__ __forceinline__ float eluf(float v) { return v > 0.f ? v : (__expf(v) - 1.f); }

// 2 edge rows per warp-LDG; weight phase software-pipelined: next block's
// ct[jn] AND dependent h1[tn] are prefetched at iteration top so their ~2x262
// cycle serial chain retires under the current block's gather phase.
__device__ __forceinline__ void agg_rel16(int lane, int lane16, int hi,
                                          int beg, int end,
                                          const int* __restrict__ ct,
                                          const uint2* __restrict__ ht4,
                                          float x1s, const float* __restrict__ h1,
                                          float& wsum, float acc[4]) {
    float a0[4] = {0, 0, 0, 0}, a1[4] = {0, 0, 0, 0};
    float a2[4] = {0, 0, 0, 0}, a3[4] = {0, 0, 0, 0};
    // preload block 0's ct + h1
    int t = 0;
    float h1v = 0.f;
    {
        int j = beg + lane;
        if (j < end) { t = ct[j]; h1v = h1[t]; }
    }
    for (int j0 = beg; j0 < end; j0 += 32) {
        // prefetch next block (loads overlap with this block's gather phase)
        int jn = j0 + 32 + lane;
        int tn = 0;
        float h1n = 0.f;
        if (jn < end) tn = ct[jn];
        float wv = 0.f;
        if (j0 + lane < end) {
            float z = x1s + h1v;
            z = z >= 0.f ? z : 0.2f * z;
            wv = __expf(z);
            wsum += wv;
        }
        if (jn < end) h1n = h1[tn];
        int cnt = min(32, end - j0);
        int ng = (cnt + 7) >> 3;
        for (int g = 0; g < ng; g++) {
            int kb = (g << 3) + hi;
            int t0 = __shfl_sync(0xffffffffu, t, kb);
            int t1 = __shfl_sync(0xffffffffu, t, kb + 2);
            int t2 = __shfl_sync(0xffffffffu, t, kb + 4);
            int t3 = __shfl_sync(0xffffffffu, t, kb + 6);
            float w0 = __shfl_sync(0xffffffffu, wv, kb);
            float w1 = __shfl_sync(0xffffffffu, wv, kb + 2);
            float w2 = __shfl_sync(0xffffffffu, wv, kb + 4);
            float w3 = __shfl_sync(0xffffffffu, wv, kb + 6);
            uint2 v0 = ht4[(size_t)t0 * 16 + lane16];
            uint2 v1 = ht4[(size_t)t1 * 16 + lane16];
            uint2 v2 = ht4[(size_t)t2 * 16 + lane16];
            uint2 v3 = ht4[(size_t)t3 * 16 + lane16];
            {
                float2 lo = __half22float2(*reinterpret_cast<__half2*>(&v0.x));
                float2 hi2 = __half22float2(*reinterpret_cast<__half2*>(&v0.y));
                a0[0] += w0 * lo.x; a0[1] += w0 * lo.y; a0[2] += w0 * hi2.x; a0[3] += w0 * hi2.y;
            }
            {
                float2 lo = __half22float2(*reinterpret_cast<__half2*>(&v1.x));
                float2 hi2 = __half22float2(*reinterpret_cast<__half2*>(&v1.y));
                a1[0] += w1 * lo.x; a1[1] += w1 * lo.y; a1[2] += w1 * hi2.x; a1[3] += w1 * hi2.y;
            }
            {
                float2 lo = __half22float2(*reinterpret_cast<__half2*>(&v2.x));
                float2 hi2 = __half22float2(*reinterpret_cast<__half2*>(&v2.y));
                a2[0] += w2 * lo.x; a2[1] += w2 * lo.y; a2[2] += w2 * hi2.x; a2[3] += w2 * hi2.y;
            }
            {
                float2 lo = __half22float2(*reinterpret_cast<__half2*>(&v3.x));
                float2 hi2 = __half22float2(*reinterpret_cast<__half2*>(&v3.y));
                a3[0] += w3 * lo.x; a3[1] += w3 * lo.y; a3[2] += w3 * hi2.x; a3[3] += w3 * hi2.y;
            }
        }
        t = tn;
        h1v = h1n;
    }
#pragma unroll
    for (int d = 0; d < 4; d++) {
        float s = (a0[d] + a1[d]) + (a2[d] + a3[d]);
        s += __shfl_xor_sync(0xffffffffu, s, 16);
        acc[d] = s;
    }
}

__device__ __forceinline__ uint2 pack4(float o0, float o1, float o2, float o3) {
    uint2 r;
    __half2 p0 = __floats2half2_rn(o0, o1);
    __half2 p1 = __floats2half2_rn(o2, o3);
    r.x = *reinterpret_cast<unsigned int*>(&p0);
    r.y = *reinterpret_cast<unsigned int*>(&p1);
    return r;
}

// Merged per-hop aggregation with fused next-hop target scalars (double-buffered).
__global__ void __launch_bounds__(256) agg_all_kernel(
        const int* __restrict__ rp_ap, const int* __restrict__ ct_ap,
        const int* __restrict__ rp_pa, const int* __restrict__ ct_pa,
        const int* __restrict__ rp_pp, const int* __restrict__ ct_pp,
        const float* __restrict__ xa, const float* __restrict__ xp,
        const uint2* __restrict__ ha, const uint2* __restrict__ hp,
        const float* __restrict__ x1_ap, const float* __restrict__ w2_ap,
        const float* __restrict__ x1_pa, const float* __restrict__ w2_pa,
        const float* __restrict__ x1_pp, const float* __restrict__ w2_pp,
        uint2* __restrict__ hao, uint2* __restrict__ hpo,
        int rb, int wb, int has_next,
        const float* __restrict__ a2ap_n, const float* __restrict__ a2pa_n,
        const float* __restrict__ a2pp_n) {
    int wrp = (blockIdx.x * blockDim.x + threadIdx.x) >> 5;
    int lane = threadIdx.x & 31;
    int lane16 = lane & 15, hi = lane >> 4;
    int d0 = 4 * lane16;

    if (wrp < NA) {
        float x1s = x1_ap[wrp];
        float wsum = 0.f;
        float acc[4];
        agg_rel16(lane, lane16, hi, rp_ap[wrp], rp_ap[wrp + 1], ct_ap, hp,
                  x1s, g_h1_ap[rb], wsum, acc);
        wsum = warp_red(wsum);
        float w2s = w2_ap[wrp];
        float inv = 1.f / (wsum + w2s);
        float4 xv = reinterpret_cast<const float4*>(xa)[(size_t)wrp * 16 + lane16];
        float o0 = eluf((acc[0] + w2s * xv.x) * inv);
        float o1 = eluf((acc[1] + w2s * xv.y) * inv);
        float o2 = eluf((acc[2] + w2s * xv.z) * inv);
        float o3 = eluf((acc[3] + w2s * xv.w) * inv);
        if (hi == 0)
            hao[(size_t)wrp * 16 + lane16] = pack4(o0, o1, o2, o3);
        if (has_next) {
            float p = o0 * a2pa_n[d0] + o1 * a2pa_n[d0 + 1]
                    + o2 * a2pa_n[d0 + 2] + o3 * a2pa_n[d0 + 3];
            p = half_red(p);
            if (lane == 0) g_h1_pa[wb][wrp] = p;
        }
    } else if (wrp < NA + NP) {
        int n = wrp - NA;
        float ws1 = 0.f;
        float accA[4];
        agg_rel16(lane, lane16, hi, rp_pa[n], rp_pa[n + 1], ct_pa, ha,
                  x1_pa[n], g_h1_pa[rb], ws1, accA);
        ws1 = warp_red(ws1);

        float ws2 = 0.f;
        float accB[4];
        agg_rel16(lane, lane16, hi, rp_pp[n], rp_pp[n + 1], ct_pp, hp,
                  x1_pp[n], g_h1_pp[rb], ws2, accB);
        ws2 = warp_red(ws2);

        float w2a = w2_pa[n];
        float w2b = w2_pp[n];
        float inv1 = 1.f / (ws1 + w2a);
        float inv2 = 1.f / (ws2 + w2b);
        float4 xv = reinterpret_cast<const float4*>(xp)[(size_t)n * 16 + lane16];
        float o0 = eluf(0.5f * ((accA[0] + w2a * xv.x) * inv1 + (accB[0] + w2b * xv.x) * inv2));
        float o1 = eluf(0.5f * ((accA[1] + w2a * xv.y) * inv1 + (accB[1] + w2b * xv.y) * inv2));
        float o2 = eluf(0.5f * ((accA[2] + w2a * xv.z) * inv1 + (accB[2] + w2b * xv.z) * inv2));
        float o3 = eluf(0.5f * ((accA[3] + w2a * xv.w) * inv1 + (accB[3] + w2b * xv.w) * inv2));
        if (hi == 0)
            hpo[(size_t)n * 16 + lane16] = pack4(o0, o1, o2, o3);
        if (has_next) {
            float p1 = o0 * a2ap_n[d0] + o1 * a2ap_n[d0 + 1]
                     + o2 * a2ap_n[d0 + 2] + o3 * a2ap_n[d0 + 3];
            float p2 = o0 * a2pp_n[d0] + o1 * a2pp_n[d0 + 1]
                     + o2 * a2pp_n[d0 + 2] + o3 * a2pp_n[d0 + 3];
            p1 = half_red(p1);
            p2 = half_red(p2);
            if (lane == 0) { g_h1_ap[wb][n] = p1; g_h1_pp[wb][n] = p2; }
        }
    }
}

// ------------------------- output projection ---------------------------------
__global__ void fc2_kernel(const __half2* __restrict__ h, const float* __restrict__ W,
                           const float* __restrict__ b, float* __restrict__ out, int n) {
    __shared__ float Ws[HH * NOUT];
    __shared__ float bs[NOUT];
    for (int i = threadIdx.x; i < HH * NOUT; i += blockDim.x) Ws[i] = W[i];
    if (threadIdx.x < NOUT) bs[threadIdx.x] = b[threadIdx.x];
    __syncthreads();
    int idx = blockIdx.x * blockDim.x + threadIdx.x;
    int node = idx >> 4, col = idx & 15;
    if (node >= n) return;
    const __half2* hr = h + (size_t)node * 32;
    float s = bs[col];
#pragma unroll
    for (int k = 0; k < 32; k++) {
        float2 f = __half22float2(hr[k]);
        s += f.x * Ws[(2 * k) * NOUT + col] + f.y * Ws[(2 * k + 1) * NOUT + col];
    }
    out[(size_t)node * NOUT + col] = s;
}

// ------------------------- host orchestration --------------------------------
extern "C" void kernel_launch(void* const* d_in, const int* in_sizes, int n_in,
                              void* d_out, int out_size) {
    const float* x_a = (const float*)d_in[0];
    const float* x_p = (const float*)d_in[1];
    const int* ap_s = (const int*)d_in[2];
    const int* ap_t = (const int*)d_in[3];
    const int* pa_s = (const int*)d_in[4];
    const int* pa_t = (const int*)d_in[5];
    const int* pp_s = (const int*)d_in[6];
    const int* pp_t = (const int*)d_in[7];
    const float* fc1_a_w = (const float*)d_in[8];
    const float* fc1_a_b = (const float*)d_in[9];
    const float* fc1_p_w = (const float*)d_in[10];
    const float* fc1_p_b = (const float*)d_in[11];
    const float* fc2_w = (const float*)d_in[12];
    const float* fc2_b = (const float*)d_in[13];
    const float* a1_ap = (const float*)d_in[14];
    const float* a2_ap = (const float*)d_in[15];
    const float* a1_pa = (const float*)d_in[16];
    const float* a2_pa = (const float*)d_in[17];
    const float* a1_pp = (const float*)d_in[18];
    const float* a2_pp = (const float*)d_in[19];
    float* out = (float*)d_out;

    int E_ap = in_sizes[2], E_pa = in_sizes[4], E_pp = in_sizes[6];
    if (E_ap > EMAX) E_ap = EMAX;
    if (E_pa > EMAX) E_pa = EMAX;
    if (E_pp > EMAX) E_pp = EMAX;
    int E_tot = E_ap + E_pa + E_pp;

    float *xa, *xp;
    cudaGetSymbolAddress((void**)&xa, g_xa);
    cudaGetSymbolAddress((void**)&xp, g_xp);
    uint2 *ha16A, *ha16B, *hp16A, *hp16B;
    cudaGetSymbolAddress((void**)&ha16A, g_ha16A);
    cudaGetSymbolAddress((void**)&ha16B, g_ha16B);
    cudaGetSymbolAddress((void**)&hp16A, g_hp16A);
    cudaGetSymbolAddress((void**)&hp16B, g_hp16B);

    int *rp_ap, *ct_ap, *rp_pa, *ct_pa, *rp_pp, *ct_pp;
    cudaGetSymbolAddress((void**)&rp_ap, g_rp_ap);
    cudaGetSymbolAddress((void**)&ct_ap, g_ct_ap);
    cudaGetSymbolAddress((void**)&rp_pa, g_rp_pa);
    cudaGetSymbolAddress((void**)&ct_pa, g_ct_pa);
    cudaGetSymbolAddress((void**)&rp_pp, g_rp_pp);
    cudaGetSymbolAddress((void**)&ct_pp, g_ct_pp);

    float *x1_ap, *w2_ap, *x1_pa, *w2_pa, *x1_pp, *w2_pp;
    cudaGetSymbolAddress((void**)&x1_ap, g_x1_ap);
    cudaGetSymbolAddress((void**)&w2_ap, g_w2_ap);
    cudaGetSymbolAddress((void**)&x1_pa, g_x1_pa);
    cudaGetSymbolAddress((void**)&w2_pa, g_w2_pa);
    cudaGetSymbolAddress((void**)&x1_pp, g_x1_pp);
    cudaGetSymbolAddress((void**)&w2_pp, g_w2_pp);

    // --- forked-stream section: CSR build (stream 0) || proj chain (sB) ---
    cudaStream_t sB;
    cudaStreamCreateWithFlags(&sB, cudaStreamNonBlocking);
    cudaEvent_t eFork, eJoin;
    cudaEventCreateWithFlags(&eFork, cudaEventDisableTiming);
    cudaEventCreateWithFlags(&eJoin, cudaEventDisableTiming);

    cudaEventRecord(eFork, 0);
    cudaStreamWaitEvent(sB, eFork, 0);

    // Branch A (stream 0): CSR build
    zero_deg_kernel<<<(NP + 255) / 256, 256>>>();
    hist_all_kernel<<<(E_tot + 255) / 256, 256>>>(ap_s, pa_s, pp_s, E_ap, E_pa, E_pp);
    scan_all_kernel<<<3, 1024>>>();
    scatter_all_kernel<<<(E_tot + 255) / 256, 256>>>(ap_s, ap_t, pa_s, pa_t, pp_s, pp_t,
                                                     E_ap, E_pa, E_pp);

    // Branch B (sB): projections -> src scalars -> hop-0 tgt scalars (bank 0)
    int nblkA = (NA + 63) / 64;
    int nblkP = (NP + 63) / 64;
    proj_tc_kernel<<<nblkA + nblkP, 256, 0, sB>>>(
        x_a, fc1_a_w, fc1_a_b, xa, (__half2*)ha16A, NA, DA, nblkA,
        x_p, fc1_p_w, fc1_p_b, xp, (__half2*)hp16A, NP, DP);
    src_all_kernel<<<((NA + NP) * 32 + 255) / 256, 256, 0, sB>>>(
        xa, xp, a1_ap, a2_ap, a1_pa, a2_pa, a1_pp, a2_pp);
    tgt_all_kernel<<<((NP + NA) * 32 + 255) / 256, 256, 0, sB>>>(
        (const __half2*)ha16A, (const __half2*)hp16A, a2_ap, a2_pa, a2_pp);

    // Join
    cudaEventRecord(eJoin, sB);
    cudaStreamWaitEvent(0, eJoin, 0);

    // --- hops; h1 double-buffered (read i&1, write (i+1)&1) ---
    const uint2* ha = ha16A;
    const uint2* hp = hp16A;
    for (int i = 0; i < NHOP; i++) {
        uint2* hao = (i & 1) ? ha16A : ha16B;
        uint2* hpo = (i & 1) ? hp16A : hp16B;
        int has_next = (i + 1 < NHOP) ? 1 : 0;
        int nx = has_next ? (i + 1) : i;

        agg_all_kernel<<<((NA + NP) * 32 + 255) / 256, 256>>>(
            rp_ap, ct_ap, rp_pa, ct_pa, rp_pp, ct_pp, xa, xp, ha, hp,
            x1_ap + i * NA, w2_ap + i * NA,
            x1_pa + i * NP, w2_pa + i * NP,
            x1_pp + i * NP, w2_pp + i * NP,
            hao, hpo,
            i & 1, (i + 1) & 1,
            has_next, a2_ap + nx * HH, a2_pa + nx * HH, a2_pp + nx * HH);
        ha = hao;
        hp = hpo;
    }

    // output projection
    fc2_kernel<<<(NA * NOUT + 255) / 256, 256>>>((const __half2*)ha, fc2_w, fc2_b, out, NA);

    cudaStreamDestroy(sB);
    cudaEventDestroy(eFork);
    cudaEventDestroy(eJoin);
}

// round 17
// speedup vs baseline: 1.1872x; 1.1701x over previous
#include <cuda_runtime.h>
#include <cuda_fp16.h>
#include <cuda_bf16.h>
#include <mma.h>
#include <cstdint>

using namespace nvcuda;

#define NA 50000
#define NP 100000
#define DA 512
#define DP 256
#define HH 64
#define NOUT 16
#define NHOP 3
#define EMAX 2000000

// ------------------------- device scratch (static; no allocs) ----------------
__device__ float g_xa[NA * HH];
__device__ float g_xp[NP * HH];
__device__ __half g_ha16A[NA * HH];
__device__ __half g_ha16B[NA * HH];
__device__ __half g_hp16A[NP * HH];
__device__ __half g_hp16B[NP * HH];

__device__ int g_deg_ap[NA];
__device__ int g_rp_ap[NA + 1];
__device__ int g_cur_ap[NA];
__device__ int g_ct_ap[EMAX];

__device__ int g_deg_pa[NP];
__device__ int g_rp_pa[NP + 1];
__device__ int g_cur_pa[NP];
__device__ int g_ct_pa[EMAX];

__device__ int g_deg_pp[NP];
__device__ int g_rp_pp[NP + 1];
__device__ int g_cur_pp[NP];
__device__ int g_ct_pp[EMAX];

__device__ float g_x1_ap[NHOP * NA], g_w2_ap[NHOP * NA];
__device__ float g_x1_pa[NHOP * NP], g_w2_pa[NHOP * NP];
__device__ float g_x1_pp[NHOP * NP], g_w2_pp[NHOP * NP];
// target-side scalars, DOUBLE-BUFFERED: hop i reads bank i&1, writes bank (i+1)&1
__device__ float g_h1_ap[2][NP], g_h1_pa[2][NA], g_h1_pp[2][NP];

// ------------------------- input projection GEMM (tensor cores) --------------
__global__ void __launch_bounds__(256) proj_tc_kernel(
        const float* __restrict__ Aa, const float* __restrict__ Wa,
        const float* __restrict__ ba, float* __restrict__ Ca,
        __half2* __restrict__ C16a, int Ma, int Ka, int nblkA,
        const float* __restrict__ Ap, const float* __restrict__ Wp,
        const float* __restrict__ bp, float* __restrict__ Cp,
        __half2* __restrict__ C16p, int Mp, int Kp) {
    const float* A; const float* W; const float* b; float* C; __half2* C16;
    int M, K, rowBase;
    if ((int)blockIdx.x < nblkA) {
        A = Aa; W = Wa; b = ba; C = Ca; C16 = C16a; M = Ma; K = Ka;
        rowBase = blockIdx.x * 64;
    } else {
        A = Ap; W = Wp; b = bp; C = Cp; C16 = C16p; M = Mp; K = Kp;
        rowBase = (blockIdx.x - nblkA) * 64;
    }

    __shared__ __align__(16) __nv_bfloat16 AsHi[64][24];
    __shared__ __align__(16) __nv_bfloat16 AsLo[64][24];
    __shared__ __align__(16) __nv_bfloat16 WsHi[16][72];
    __shared__ __align__(16) __nv_bfloat16 WsLo[16][72];
    __shared__ __align__(16) float Outs[64][68];
    __shared__ float bs[64];

    int tid = threadIdx.x;
    int wid = tid >> 5;
    int wr = wid >> 1;
    int wc = wid & 1;

    if (tid < 64) bs[tid] = b[tid];

    wmma::fragment<wmma::accumulator, 16, 16, 16, float> acc[2];
    wmma::fill_fragment(acc[0], 0.f);
    wmma::fill_fragment(acc[1], 0.f);

    int nk = K >> 4;
    for (int ks = 0; ks < nk; ks++) {
        int k0 = ks << 4;
        {
            int row = tid >> 2;
            int q = (tid & 3) * 4;
            float4 v = make_float4(0.f, 0.f, 0.f, 0.f);
            int gr = rowBase + row;
            if (gr < M) v = *reinterpret_cast<const float4*>(&A[(size_t)gr * K + k0 + q]);
            float vv[4] = {v.x, v.y, v.z, v.w};
#pragma unroll
            for (int j = 0; j < 4; j++) {
                __nv_bfloat16 h = __float2bfloat16_rn(vv[j]);
                AsHi[row][q + j] = h;
                AsLo[row][q + j] = __float2bfloat16_rn(vv[j] - __bfloat162float(h));
            }
        }
        {
            int row = tid >> 4;
            int c = (tid & 15) * 4;
            float4 v = *reinterpret_cast<const float4*>(&W[(size_t)(k0 + row) * 64 + c]);
            float vv[4] = {v.x, v.y, v.z, v.w};
#pragma unroll
            for (int j = 0; j < 4; j++) {
                __nv_bfloat16 h = __float2bfloat16_rn(vv[j]);
                WsHi[row][c + j] = h;
                WsLo[row][c + j] = __float2bfloat16_rn(vv[j] - __bfloat162float(h));
            }
        }
        __syncthreads();

        wmma::fragment<wmma::matrix_a, 16, 16, 16, __nv_bfloat16, wmma::row_major> aHi, aLo;
        wmma::load_matrix_sync(aHi, &AsHi[wr * 16][0], 24);
        wmma::load_matrix_sync(aLo, &AsLo[wr * 16][0], 24);
#pragma unroll
        for (int t = 0; t < 2; t++) {
            int c0 = wc * 32 + t * 16;
            wmma::fragment<wmma::matrix_b, 16, 16, 16, __nv_bfloat16, wmma::row_major> bHi, bLo;
            wmma::load_matrix_sync(bHi, &WsHi[0][c0], 72);
            wmma::load_matrix_sync(bLo, &WsLo[0][c0], 72);
            wmma::mma_sync(acc[t], aHi, bHi, acc[t]);
            wmma::mma_sync(acc[t], aLo, bHi, acc[t]);
            wmma::mma_sync(acc[t], aHi, bLo, acc[t]);
        }
        __syncthreads();
    }

#pragma unroll
    for (int t = 0; t < 2; t++)
        wmma::store_matrix_sync(&Outs[wr * 16][wc * 32 + t * 16], acc[t], 68,
                                wmma::mem_row_major);
    __syncthreads();

#pragma unroll
    for (int it = 0; it < 8; it++) {
        int p = tid + it * 256;
        int row = p >> 5;
        int c2 = (p & 31) * 2;
        int gr = rowBase + row;
        if (gr < M) {
            float v0 = Outs[row][c2] + bs[c2];
            float v1 = Outs[row][c2 + 1] + bs[c2 + 1];
            v0 = v0 > 0.f ? v0 : 0.f;
            v1 = v1 > 0.f ? v1 : 0.f;
            C[(size_t)gr * 64 + c2] = v0;
            C[(size_t)gr * 64 + c2 + 1] = v1;
            C16[(size_t)gr * 32 + (c2 >> 1)] = __floats2half2_rn(v0, v1);
        }
    }
}

// ------------------------- CSR build ----------------------------------------
__global__ void zero_deg_kernel() {
    int i = blockIdx.x * blockDim.x + threadIdx.x;
    if (i < NA) g_deg_ap[i] = 0;
    if (i < NP) { g_deg_pa[i] = 0; g_deg_pp[i] = 0; }
}

__global__ void hist_all_kernel(const int* __restrict__ s_ap, const int* __restrict__ s_pa,
                                const int* __restrict__ s_pp, int Eap, int Epa, int Epp) {
    int i = blockIdx.x * blockDim.x + threadIdx.x;
    int tot = Eap + Epa + Epp;
    if (i >= tot) return;
    if (i < Eap) atomicAdd(&g_deg_ap[s_ap[i]], 1);
    else if (i < Eap + Epa) atomicAdd(&g_deg_pa[s_pa[i - Eap]], 1);
    else atomicAdd(&g_deg_pp[s_pp[i - Eap - Epa]], 1);
}

__device__ void scan_block(const int* __restrict__ deg, int* __restrict__ rp,
                           int* __restrict__ cur, int n) {
    __shared__ int carry;
    __shared__ int wsum[32];
    if (threadIdx.x == 0) carry = 0;
    __syncthreads();
    int lane = threadIdx.x & 31, wid = threadIdx.x >> 5;
    for (int base = 0; base < n; base += 1024) {
        int i = base + threadIdx.x;
        int v = (i < n) ? deg[i] : 0;
        int x = v;
#pragma unroll
        for (int o = 1; o < 32; o <<= 1) {
            int y = __shfl_up_sync(0xffffffffu, x, o);
            if (lane >= o) x += y;
        }
        if (lane == 31) wsum[wid] = x;
        __syncthreads();
        if (wid == 0) {
            int sv = wsum[lane];
#pragma unroll
            for (int o = 1; o < 32; o <<= 1) {
                int y = __shfl_up_sync(0xffffffffu, sv, o);
                if (lane >= o) sv += y;
            }
            wsum[lane] = sv;
        }
        __syncthreads();
        int excl = carry + x - v + ((wid > 0) ? wsum[wid - 1] : 0);
        if (i < n) { rp[i] = excl; cur[i] = excl; }
        int tot = wsum[31];
        __syncthreads();
        if (threadIdx.x == 0) carry += tot;
        __syncthreads();
    }
    if (threadIdx.x == 0) rp[n] = carry;
}

__global__ void scan_all_kernel() {
    if (blockIdx.x == 0) scan_block(g_deg_ap, g_rp_ap, g_cur_ap, NA);
    else if (blockIdx.x == 1) scan_block(g_deg_pa, g_rp_pa, g_cur_pa, NP);
    else scan_block(g_deg_pp, g_rp_pp, g_cur_pp, NP);
}

__global__ void scatter_all_kernel(const int* __restrict__ s_ap, const int* __restrict__ t_ap,
                                   const int* __restrict__ s_pa, const int* __restrict__ t_pa,
                                   const int* __restrict__ s_pp, const int* __restrict__ t_pp,
                                   int Eap, int Epa, int Epp) {
    int i = blockIdx.x * blockDim.x + threadIdx.x;
    int tot = Eap + Epa + Epp;
    if (i >= tot) return;
    if (i < Eap) {
        int pos = atomicAdd(&g_cur_ap[s_ap[i]], 1);
        g_ct_ap[pos] = t_ap[i];
    } else if (i < Eap + Epa) {
        int j = i - Eap;
        int pos = atomicAdd(&g_cur_pa[s_pa[j]], 1);
        g_ct_pa[pos] = t_pa[j];
    } else {
        int j = i - Eap - Epa;
        int pos = atomicAdd(&g_cur_pp[s_pp[j]], 1);
        g_ct_pp[pos] = t_pp[j];
    }
}

// ------------------------- scalar precompute ---------------------------------
__device__ __forceinline__ float warp_red(float s) {
#pragma unroll
    for (int o = 16; o; o >>= 1) s += __shfl_xor_sync(0xffffffffu, s, o);
    return s;
}

__device__ __forceinline__ float half_red(float s) {
#pragma unroll
    for (int o = 8; o; o >>= 1) s += __shfl_xor_sync(0xffffffffu, s, o);
    return s;
}

__global__ void src_all_kernel(const float* __restrict__ xa, const float* __restrict__ xp,
                               const float* __restrict__ a1ap, const float* __restrict__ a2ap,
                               const float* __restrict__ a1pa, const float* __restrict__ a2pa,
                               const float* __restrict__ a1pp, const float* __restrict__ a2pp) {
    int w = (blockIdx.x * blockDim.x + threadIdx.x) >> 5;
    int lane = threadIdx.x & 31;
    if (w < NA) {
        const float* xr = xa + (size_t)w * HH;
        float v0 = xr[lane], v1 = xr[lane + 32];
#pragma unroll
        for (int i = 0; i < NHOP; i++) {
            float s1 = warp_red(v0 * a1ap[i * HH + lane] + v1 * a1ap[i * HH + lane + 32]);
            float s2 = warp_red(v0 * a2ap[i * HH + lane] + v1 * a2ap[i * HH + lane + 32]);
            if (lane == 0) {
                g_x1_ap[i * NA + w] = s1;
                float z = s1 + s2;
                z = z >= 0.f ? z : 0.2f * z;
                g_w2_ap[i * NA + w] = __expf(z);
            }
        }
    } else if (w < NA + NP) {
        int n = w - NA;
        const float* xr = xp + (size_t)n * HH;
        float v0 = xr[lane], v1 = xr[lane + 32];
#pragma unroll
        for (int i = 0; i < NHOP; i++) {
            float s1 = warp_red(v0 * a1pa[i * HH + lane] + v1 * a1pa[i * HH + lane + 32]);
            float s2 = warp_red(v0 * a2pa[i * HH + lane] + v1 * a2pa[i * HH + lane + 32]);
            float s3 = warp_red(v0 * a1pp[i * HH + lane] + v1 * a1pp[i * HH + lane + 32]);
            float s4 = warp_red(v0 * a2pp[i * HH + lane] + v1 * a2pp[i * HH + lane + 32]);
            if (lane == 0) {
                g_x1_pa[i * NP + n] = s1;
                float z = s1 + s2;
                z = z >= 0.f ? z : 0.2f * z;
                g_w2_pa[i * NP + n] = __expf(z);
                g_x1_pp[i * NP + n] = s3;
                float z2 = s3 + s4;
                z2 = z2 >= 0.f ? z2 : 0.2f * z2;
                g_w2_pp[i * NP + n] = __expf(z2);
            }
        }
    }
}

// hop-0 target scalars (writes bank 0; runs overlapped with CSR build)
__global__ void tgt_all_kernel(const __half2* __restrict__ ha16,
                               const __half2* __restrict__ hp16,
                               const float* __restrict__ a2ap,
                               const float* __restrict__ a2pa,
                               const float* __restrict__ a2pp) {
    int w = (blockIdx.x * blockDim.x + threadIdx.x) >> 5;
    int lane = threadIdx.x & 31;
    if (w < NP) {
        float2 f = __half22float2(hp16[(size_t)w * 32 + lane]);
        float s1 = warp_red(f.x * a2ap[2 * lane] + f.y * a2ap[2 * lane + 1]);
        float s2 = warp_red(f.x * a2pp[2 * lane] + f.y * a2pp[2 * lane + 1]);
        if (lane == 0) { g_h1_ap[0][w] = s1; g_h1_pp[0][w] = s2; }
    } else if (w < NP + NA) {
        int n = w - NP;
        float2 f = __half22float2(ha16[(size_t)n * 32 + lane]);
        float s = warp_red(f.x * a2pa[2 * lane] + f.y * a2pa[2 * lane + 1]);
        if (lane == 0) g_h1_pa[0][n] = s;
    }
}

// ------------------------- aggregation --------------------------------------
__device__ __forceinline__ float eluf(float v) { return v > 0.f ? v : (__expf(v) - 1.f); }

// Round-11 (best measured) loop: 2 edge rows per warp-LDG, no pipelining.
__device__ __forceinline__ void agg_rel16(int lane, int lane16, int hi,
                                          int beg, int end,
                                          const int* __restrict__ ct,
                                          const uint2* __restrict__ ht4,
                                          float x1s, const float* __restrict__ h1,
                                          float& wsum, float acc[4]) {
    float a0[4] = {0, 0, 0, 0}, a1[4] = {0, 0, 0, 0};
    float a2[4] = {0, 0, 0, 0}, a3[4] = {0, 0, 0, 0};
    for (int j0 = beg; j0 < end; j0 += 32) {
        int j = j0 + lane;
        float wv = 0.f;
        int t = 0;
        if (j < end) {
            t = ct[j];
            float z = x1s + h1[t];
            z = z >= 0.f ? z : 0.2f * z;
            wv = __expf(z);
            wsum += wv;
        }
        int cnt = min(32, end - j0);
        int ng = (cnt + 7) >> 3;
        for (int g = 0; g < ng; g++) {
            int kb = (g << 3) + hi;
            int t0 = __shfl_sync(0xffffffffu, t, kb);
            int t1 = __shfl_sync(0xffffffffu, t, kb + 2);
            int t2 = __shfl_sync(0xffffffffu, t, kb + 4);
            int t3 = __shfl_sync(0xffffffffu, t, kb + 6);
            float w0 = __shfl_sync(0xffffffffu, wv, kb);
            float w1 = __shfl_sync(0xffffffffu, wv, kb + 2);
            float w2 = __shfl_sync(0xffffffffu, wv, kb + 4);
            float w3 = __shfl_sync(0xffffffffu, wv, kb + 6);
            uint2 v0 = ht4[(size_t)t0 * 16 + lane16];
            uint2 v1 = ht4[(size_t)t1 * 16 + lane16];
            uint2 v2 = ht4[(size_t)t2 * 16 + lane16];
            uint2 v3 = ht4[(size_t)t3 * 16 + lane16];
            {
                float2 lo = __half22float2(*reinterpret_cast<__half2*>(&v0.x));
                float2 hi2 = __half22float2(*reinterpret_cast<__half2*>(&v0.y));
                a0[0] += w0 * lo.x; a0[1] += w0 * lo.y; a0[2] += w0 * hi2.x; a0[3] += w0 * hi2.y;
            }
            {
                float2 lo = __half22float2(*reinterpret_cast<__half2*>(&v1.x));
                float2 hi2 = __half22float2(*reinterpret_cast<__half2*>(&v1.y));
                a1[0] += w1 * lo.x; a1[1] += w1 * lo.y; a1[2] += w1 * hi2.x; a1[3] += w1 * hi2.y;
            }
            {
                float2 lo = __half22float2(*reinterpret_cast<__half2*>(&v2.x));
                float2 hi2 = __half22float2(*reinterpret_cast<__half2*>(&v2.y));
                a2[0] += w2 * lo.x; a2[1] += w2 * lo.y; a2[2] += w2 * hi2.x; a2[3] += w2 * hi2.y;
            }
            {
                float2 lo = __half22float2(*reinterpret_cast<__half2*>(&v3.x));
                float2 hi2 = __half22float2(*reinterpret_cast<__half2*>(&v3.y));
                a3[0] += w3 * lo.x; a3[1] += w3 * lo.y; a3[2] += w3 * hi2.x; a3[3] += w3 * hi2.y;
            }
        }
    }
#pragma unroll
    for (int d = 0; d < 4; d++) {
        float s = (a0[d] + a1[d]) + (a2[d] + a3[d]);
        s += __shfl_xor_sync(0xffffffffu, s, 16);
        acc[d] = s;
    }
}

__device__ __forceinline__ uint2 pack4(float o0, float o1, float o2, float o3) {
    uint2 r;
    __half2 p0 = __floats2half2_rn(o0, o1);
    __half2 p1 = __floats2half2_rn(o2, o3);
    r.x = *reinterpret_cast<unsigned int*>(&p0);
    r.y = *reinterpret_cast<unsigned int*>(&p1);
    return r;
}

// Merged per-hop aggregation with fused next-hop target scalars (double-buffered).
// Last hop is launched with grid covering only NA warps (p-branch is dead code:
// final h_p is never consumed by the model output).
__global__ void __launch_bounds__(256) agg_all_kernel(
        const int* __restrict__ rp_ap, const int* __restrict__ ct_ap,
        const int* __restrict__ rp_pa, const int* __restrict__ ct_pa,
        const int* __restrict__ rp_pp, const int* __restrict__ ct_pp,
        const float* __restrict__ xa, const float* __restrict__ xp,
        const uint2* __restrict__ ha, const uint2* __restrict__ hp,
        const float* __restrict__ x1_ap, const float* __restrict__ w2_ap,
        const float* __restrict__ x1_pa, const float* __restrict__ w2_pa,
        const float* __restrict__ x1_pp, const float* __restrict__ w2_pp,
        uint2* __restrict__ hao, uint2* __restrict__ hpo,
        int rb, int wb, int has_next,
        const float* __restrict__ a2ap_n, const float* __restrict__ a2pa_n,
        const float* __restrict__ a2pp_n) {
    int wrp = (blockIdx.x * blockDim.x + threadIdx.x) >> 5;
    int lane = threadIdx.x & 31;
    int lane16 = lane & 15, hi = lane >> 4;
    int d0 = 4 * lane16;

    if (wrp < NA) {
        float x1s = x1_ap[wrp];
        float wsum = 0.f;
        float acc[4];
        agg_rel16(lane, lane16, hi, rp_ap[wrp], rp_ap[wrp + 1], ct_ap, hp,
                  x1s, g_h1_ap[rb], wsum, acc);
        wsum = warp_red(wsum);
        float w2s = w2_ap[wrp];
        float inv = 1.f / (wsum + w2s);
        float4 xv = reinterpret_cast<const float4*>(xa)[(size_t)wrp * 16 + lane16];
        float o0 = eluf((acc[0] + w2s * xv.x) * inv);
        float o1 = eluf((acc[1] + w2s * xv.y) * inv);
        float o2 = eluf((acc[2] + w2s * xv.z) * inv);
        float o3 = eluf((acc[3] + w2s * xv.w) * inv);
        if (hi == 0)
            hao[(size_t)wrp * 16 + lane16] = pack4(o0, o1, o2, o3);
        if (has_next) {
            float p = o0 * a2pa_n[d0] + o1 * a2pa_n[d0 + 1]
                    + o2 * a2pa_n[d0 + 2] + o3 * a2pa_n[d0 + 3];
            p = half_red(p);
            if (lane == 0) g_h1_pa[wb][wrp] = p;
        }
    } else if (wrp < NA + NP) {
        int n = wrp - NA;
        float ws1 = 0.f;
        float accA[4];
        agg_rel16(lane, lane16, hi, rp_pa[n], rp_pa[n + 1], ct_pa, ha,
                  x1_pa[n], g_h1_pa[rb], ws1, accA);
        ws1 = warp_red(ws1);

        float ws2 = 0.f;
        float accB[4];
        agg_rel16(lane, lane16, hi, rp_pp[n], rp_pp[n + 1], ct_pp, hp,
                  x1_pp[n], g_h1_pp[rb], ws2, accB);
        ws2 = warp_red(ws2);

        float w2a = w2_pa[n];
        float w2b = w2_pp[n];
        float inv1 = 1.f / (ws1 + w2a);
        float inv2 = 1.f / (ws2 + w2b);
        float4 xv = reinterpret_cast<const float4*>(xp)[(size_t)n * 16 + lane16];
        float o0 = eluf(0.5f * ((accA[0] + w2a * xv.x) * inv1 + (accB[0] + w2b * xv.x) * inv2));
        float o1 = eluf(0.5f * ((accA[1] + w2a * xv.y) * inv1 + (accB[1] + w2b * xv.y) * inv2));
        float o2 = eluf(0.5f * ((accA[2] + w2a * xv.z) * inv1 + (accB[2] + w2b * xv.z) * inv2));
        float o3 = eluf(0.5f * ((accA[3] + w2a * xv.w) * inv1 + (accB[3] + w2b * xv.w) * inv2));
        if (hi == 0)
            hpo[(size_t)n * 16 + lane16] = pack4(o0, o1, o2, o3);
        if (has_next) {
            float p1 = o0 * a2ap_n[d0] + o1 * a2ap_n[d0 + 1]
                     + o2 * a2ap_n[d0 + 2] + o3 * a2ap_n[d0 + 3];
            float p2 = o0 * a2pp_n[d0] + o1 * a2pp_n[d0 + 1]
                     + o2 * a2pp_n[d0 + 2] + o3 * a2pp_n[d0 + 3];
            p1 = half_red(p1);
            p2 = half_red(p2);
            if (lane == 0) { g_h1_ap[wb][n] = p1; g_h1_pp[wb][n] = p2; }
        }
    }
}

// ------------------------- output projection ---------------------------------
__global__ void fc2_kernel(const __half2* __restrict__ h, const float* __restrict__ W,
                           const float* __restrict__ b, float* __restrict__ out, int n) {
    __shared__ float Ws[HH * NOUT];
    __shared__ float bs[NOUT];
    for (int i = threadIdx.x; i < HH * NOUT; i += blockDim.x) Ws[i] = W[i];
    if (threadIdx.x < NOUT) bs[threadIdx.x] = b[threadIdx.x];
    __syncthreads();
    int idx = blockIdx.x * blockDim.x + threadIdx.x;
    int node = idx >> 4, col = idx & 15;
    if (node >= n) return;
    const __half2* hr = h + (size_t)node * 32;
    float s = bs[col];
#pragma unroll
    for (int k = 0; k < 32; k++) {
        float2 f = __half22float2(hr[k]);
        s += f.x * Ws[(2 * k) * NOUT + col] + f.y * Ws[(2 * k + 1) * NOUT + col];
    }
    out[(size_t)node * NOUT + col] = s;
}

// ------------------------- host orchestration --------------------------------
extern "C" void kernel_launch(void* const* d_in, const int* in_sizes, int n_in,
                              void* d_out, int out_size) {
    const float* x_a = (const float*)d_in[0];
    const float* x_p = (const float*)d_in[1];
    const int* ap_s = (const int*)d_in[2];
    const int* ap_t = (const int*)d_in[3];
    const int* pa_s = (const int*)d_in[4];
    const int* pa_t = (const int*)d_in[5];
    const int* pp_s = (const int*)d_in[6];
    const int* pp_t = (const int*)d_in[7];
    const float* fc1_a_w = (const float*)d_in[8];
    const float* fc1_a_b = (const float*)d_in[9];
    const float* fc1_p_w = (const float*)d_in[10];
    const float* fc1_p_b = (const float*)d_in[11];
    const float* fc2_w = (const float*)d_in[12];
    const float* fc2_b = (const float*)d_in[13];
    const float* a1_ap = (const float*)d_in[14];
    const float* a2_ap = (const float*)d_in[15];
    const float* a1_pa = (const float*)d_in[16];
    const float* a2_pa = (const float*)d_in[17];
    const float* a1_pp = (const float*)d_in[18];
    const float* a2_pp = (const float*)d_in[19];
    float* out = (float*)d_out;

    int E_ap = in_sizes[2], E_pa = in_sizes[4], E_pp = in_sizes[6];
    if (E_ap > EMAX) E_ap = EMAX;
    if (E_pa > EMAX) E_pa = EMAX;
    if (E_pp > EMAX) E_pp = EMAX;
    int E_tot = E_ap + E_pa + E_pp;

    float *xa, *xp;
    cudaGetSymbolAddress((void**)&xa, g_xa);
    cudaGetSymbolAddress((void**)&xp, g_xp);
    uint2 *ha16A, *ha16B, *hp16A, *hp16B;
    cudaGetSymbolAddress((void**)&ha16A, g_ha16A);
    cudaGetSymbolAddress((void**)&ha16B, g_ha16B);
    cudaGetSymbolAddress((void**)&hp16A, g_hp16A);
    cudaGetSymbolAddress((void**)&hp16B, g_hp16B);

    int *rp_ap, *ct_ap, *rp_pa, *ct_pa, *rp_pp, *ct_pp;
    cudaGetSymbolAddress((void**)&rp_ap, g_rp_ap);
    cudaGetSymbolAddress((void**)&ct_ap, g_ct_ap);
    cudaGetSymbolAddress((void**)&rp_pa, g_rp_pa);
    cudaGetSymbolAddress((void**)&ct_pa, g_ct_pa);
    cudaGetSymbolAddress((void**)&rp_pp, g_rp_pp);
    cudaGetSymbolAddress((void**)&ct_pp, g_ct_pp);

    float *x1_ap, *w2_ap, *x1_pa, *w2_pa, *x1_pp, *w2_pp;
    cudaGetSymbolAddress((void**)&x1_ap, g_x1_ap);
    cudaGetSymbolAddress((void**)&w2_ap, g_w2_ap);
    cudaGetSymbolAddress((void**)&x1_pa, g_x1_pa);
    cudaGetSymbolAddress((void**)&w2_pa, g_w2_pa);
    cudaGetSymbolAddress((void**)&x1_pp, g_x1_pp);
    cudaGetSymbolAddress((void**)&w2_pp, g_w2_pp);

    // --- forked-stream section: CSR build (stream 0) || proj chain (sB) ---
    cudaStream_t sB;
    cudaStreamCreateWithFlags(&sB, cudaStreamNonBlocking);
    cudaEvent_t eFork, eJoin;
    cudaEventCreateWithFlags(&eFork, cudaEventDisableTiming);
    cudaEventCreateWithFlags(&eJoin, cudaEventDisableTiming);

    cudaEventRecord(eFork, 0);
    cudaStreamWaitEvent(sB, eFork, 0);

    // Branch A (stream 0): CSR build
    zero_deg_kernel<<<(NP + 255) / 256, 256>>>();
    hist_all_kernel<<<(E_tot + 255) / 256, 256>>>(ap_s, pa_s, pp_s, E_ap, E_pa, E_pp);
    scan_all_kernel<<<3, 1024>>>();
    scatter_all_kernel<<<(E_tot + 255) / 256, 256>>>(ap_s, ap_t, pa_s, pa_t, pp_s, pp_t,
                                                     E_ap, E_pa, E_pp);

    // Branch B (sB): projections -> src scalars -> hop-0 tgt scalars (bank 0)
    int nblkA = (NA + 63) / 64;
    int nblkP = (NP + 63) / 64;
    proj_tc_kernel<<<nblkA + nblkP, 256, 0, sB>>>(
        x_a, fc1_a_w, fc1_a_b, xa, (__half2*)ha16A, NA, DA, nblkA,
        x_p, fc1_p_w, fc1_p_b, xp, (__half2*)hp16A, NP, DP);
    src_all_kernel<<<((NA + NP) * 32 + 255) / 256, 256, 0, sB>>>(
        xa, xp, a1_ap, a2_ap, a1_pa, a2_pa, a1_pp, a2_pp);
    tgt_all_kernel<<<((NP + NA) * 32 + 255) / 256, 256, 0, sB>>>(
        (const __half2*)ha16A, (const __half2*)hp16A, a2_ap, a2_pa, a2_pp);

    // Join
    cudaEventRecord(eJoin, sB);
    cudaStreamWaitEvent(0, eJoin, 0);

    // --- hops; h1 double-buffered; LAST hop launches only a-node warps ---
    const uint2* ha = ha16A;
    const uint2* hp = hp16A;
    for (int i = 0; i < NHOP; i++) {
        uint2* hao = (i & 1) ? ha16A : ha16B;
        uint2* hpo = (i & 1) ? hp16A : hp16B;
        int has_next = (i + 1 < NHOP) ? 1 : 0;
        int nx = has_next ? (i + 1) : i;
        // final h_p is never consumed -> skip p-node aggregation on last hop
        int nwarps = has_next ? (NA + NP) : NA;

        agg_all_kernel<<<(nwarps * 32 + 255) / 256, 256>>>(
            rp_ap, ct_ap, rp_pa, ct_pa, rp_pp, ct_pp, xa, xp, ha, hp,
            x1_ap + i * NA, w2_ap + i * NA,
            x1_pa + i * NP, w2_pa + i * NP,
            x1_pp + i * NP, w2_pp + i * NP,
            hao, hpo,
            i & 1, (i + 1) & 1,
            has_next, a2_ap + nx * HH, a2_pa + nx * HH, a2_pp + nx * HH);
        ha = hao;
        hp = hpo;
    }

    // output projection
    fc2_kernel<<<(NA * NOUT + 255) / 256, 256>>>((const __half2*)ha, fc2_w, fc2_b, out, NA);

    cudaStreamDestroy(sB);
    cudaEventDestroy(eFork);
    cudaEventDestroy(eJoin);
}